// round 2
// baseline (speedup 1.0000x reference)
#include <cuda_runtime.h>

#define B_   2
#define H_   8
#define G_   16
#define S_   2048
#define E_   64
#define DM   512
#define CT   32
#define CH   (S_/CT)          /* 64 chunks */
#define NCHAIN (B_*H_*G_)     /* 256 scan chains */
#define REC  132              /* record: [0]=Nw, [1..64]=Sk, [65..128]=Sv */

// ---------------- scratch (static device allocations only) ----------------
__device__ float  g_qs[B_*H_*S_*E_];
__device__ float  g_kk[B_*H_*S_*E_];
__device__ float  g_vs[B_*H_*S_*E_];
__device__ float  g_cs[B_*H_*G_*E_];
__device__ float  g_scores[NCHAIN*S_];
__device__ float  g_wexp[NCHAIN*S_];
__device__ float  g_chunk[NCHAIN*CH*REC];
__device__ float  g_attn[B_*S_*DM];
__device__ double g_partial[NCHAIN];
__device__ float  g_mean;

// ---------------- generic 512-K fp32 GEMM, 64x64 tile, 256 threads --------
// mode 0: C row-major (M x 512)
// mode 1: head-split output: m=b*rowsPer+r, n=h*64+e -> C[((b*H+h)*rowsPer+r)*64+e]
__global__ __launch_bounds__(256) void gemm512(
    const float* __restrict__ A, const float* __restrict__ W,
    float* __restrict__ C, int M, int mode, int rowsPer)
{
    __shared__ float As[16][65];
    __shared__ float Bs[16][64];
    int tid = threadIdx.x;
    int tx = tid & 15, ty = tid >> 4;
    int ty4 = ty << 2, tx4 = tx << 2;
    int m0 = blockIdx.x * 64, n0 = blockIdx.y * 64;
    int arow = tid >> 2, acol = (tid & 3) << 2;
    int brow = tid >> 4, bcol = (tid & 15) << 2;

    float acc[4][4];
#pragma unroll
    for (int i = 0; i < 4; i++)
#pragma unroll
        for (int j = 0; j < 4; j++) acc[i][j] = 0.f;

    for (int k0 = 0; k0 < DM; k0 += 16) {
        float4 av = make_float4(0.f, 0.f, 0.f, 0.f);
        if (m0 + arow < M)
            av = *(const float4*)&A[(size_t)(m0 + arow) * DM + k0 + acol];
        As[acol + 0][arow] = av.x;
        As[acol + 1][arow] = av.y;
        As[acol + 2][arow] = av.z;
        As[acol + 3][arow] = av.w;
        float4 bv = *(const float4*)&W[(size_t)(k0 + brow) * DM + n0 + bcol];
        *(float4*)&Bs[brow][bcol] = bv;
        __syncthreads();
#pragma unroll
        for (int k = 0; k < 16; k++) {
            float a0 = As[k][ty4 + 0], a1 = As[k][ty4 + 1];
            float a2 = As[k][ty4 + 2], a3 = As[k][ty4 + 3];
            float4 b4 = *(float4*)&Bs[k][tx4];
            acc[0][0] += a0 * b4.x; acc[0][1] += a0 * b4.y; acc[0][2] += a0 * b4.z; acc[0][3] += a0 * b4.w;
            acc[1][0] += a1 * b4.x; acc[1][1] += a1 * b4.y; acc[1][2] += a1 * b4.z; acc[1][3] += a1 * b4.w;
            acc[2][0] += a2 * b4.x; acc[2][1] += a2 * b4.y; acc[2][2] += a2 * b4.z; acc[2][3] += a2 * b4.w;
            acc[3][0] += a3 * b4.x; acc[3][1] += a3 * b4.y; acc[3][2] += a3 * b4.z; acc[3][3] += a3 * b4.w;
        }
        __syncthreads();
    }

#pragma unroll
    for (int i = 0; i < 4; i++) {
        int m = m0 + ty4 + i;
        if (m >= M) continue;
        int n = n0 + tx4;
        float4 v = make_float4(acc[i][0], acc[i][1], acc[i][2], acc[i][3]);
        if (mode == 0) {
            *(float4*)&C[(size_t)m * DM + n] = v;
        } else {
            int b = m / rowsPer, r = m - b * rowsPer;
            int h = n >> 6, e = n & 63;
            *(float4*)&C[((size_t)(b * H_ + h) * rowsPer + r) * E_ + e] = v;
        }
    }
}

// ---------------- scores[b,h,g,s] = (cs . kk)/8 + per-chain fp64 partial --
__global__ __launch_bounds__(256) void scores_kernel()
{
    int chain = blockIdx.x;         // (b*H+h)*G + g
    int bh = chain >> 4;
    __shared__ float csh[64];
    __shared__ double dsh[8];
    int tid = threadIdx.x, lane = tid & 31, wp = tid >> 5;
    if (tid < 64) csh[tid] = g_cs[(size_t)chain * E_ + tid];
    __syncthreads();
    double local = 0.0;
    for (int s = wp; s < S_; s += 8) {
        const float* kp = g_kk + ((size_t)bh * S_ + s) * E_;
        float d = csh[lane] * kp[lane] + csh[lane + 32] * kp[lane + 32];
#pragma unroll
        for (int o = 16; o; o >>= 1) d += __shfl_xor_sync(0xffffffffu, d, o);
        if (lane == 0) {
            d *= 0.125f;  // 1/sqrt(64)
            g_scores[(size_t)chain * S_ + s] = d;
            local += (double)d;
        }
    }
    if (lane == 0) dsh[wp] = local;
    __syncthreads();
    if (tid == 0) {
        double t = 0.0;
        for (int i = 0; i < 8; i++) t += dsh[i];
        g_partial[chain] = t;
    }
}

// ---------------- deterministic mean reduction ----------------------------
__global__ __launch_bounds__(256) void mean_kernel()
{
    __shared__ double sh[256];
    int t = threadIdx.x;
    sh[t] = g_partial[t];
    __syncthreads();
    for (int o = 128; o; o >>= 1) {
        if (t < o) sh[t] += sh[t + o];
        __syncthreads();
    }
    if (t == 0) g_mean = (float)(sh[0] / (double)((size_t)NCHAIN * S_));
}

// ---------------- w = exp(score - mean) -----------------------------------
__global__ __launch_bounds__(256) void wexp_kernel()
{
    int i = blockIdx.x * 256 + threadIdx.x;
    g_wexp[i] = expf(g_scores[i] - g_mean);
}

// ---------------- per-chunk partial sums ----------------------------------
__global__ __launch_bounds__(64) void chunk_sums_kernel()
{
    int chain = blockIdx.x, c = blockIdx.y;
    int tid = threadIdx.x;          // 64 threads = one e each
    int bh = chain >> 4;
    __shared__ float wsh[CT];
    if (tid < CT) wsh[tid] = g_wexp[(size_t)chain * S_ + c * CT + tid];
    __syncthreads();
    const float* kb = g_kk + ((size_t)bh * S_ + c * CT) * E_ + tid;
    const float* vb = g_vs + ((size_t)bh * S_ + c * CT) * E_ + tid;
    float ak = 0.f, av = 0.f;
#pragma unroll 8
    for (int t = 0; t < CT; t++) {
        float w = wsh[t];
        ak += w * kb[t * E_];
        av += w * vb[t * E_];
    }
    float* op = g_chunk + ((size_t)chain * CH + c) * REC;
    op[1 + tid] = ak;
    op[65 + tid] = av;
    if (tid == 0) {
        float s = 0.f;
        for (int t = 0; t < CT; t++) s += wsh[t];
        op[0] = s;
    }
}

// ---------------- exclusive prefix over chunks (per chain) ----------------
__global__ __launch_bounds__(160) void chunk_prefix_kernel()
{
    int chain = blockIdx.x;
    int t = threadIdx.x;
    if (t >= 129) return;
    float run = 0.f;
    for (int c = 0; c < CH; c++) {
        size_t idx = ((size_t)chain * CH + c) * REC + t;
        float v = g_chunk[idx];
        g_chunk[idx] = run;
        run += v;
    }
}

// ---------------- main fused scan + softmax-over-g + output ---------------
// grid (B*H, CH), 512 threads = 16 warps, warp g owns chain (bh,g) state in regs
__global__ __launch_bounds__(512) void attn_scan_kernel()
{
    int bh = blockIdx.x;            // 0..15
    int c  = blockIdx.y;            // 0..63
    int tid = threadIdx.x;
    int g = tid >> 5, lane = tid & 31;

    __shared__ float kkS[64], vsS[64], qsS[64];
    __shared__ float wl[16];
    __shared__ float pn[16];
    __shared__ float ybuf[16][64];

    const float* pf = g_chunk + ((size_t)(bh * G_ + g) * CH + c) * REC;
    float nw  = pf[0];
    float skA = pf[1 + lane];
    float skB = pf[1 + 32 + lane];
    float svA = pf[65 + lane];
    float svB = pf[65 + 32 + lane];

    // lane t holds w for step t of this chunk (chain = bh*G+g)
    float wchunk = g_wexp[(size_t)(bh * G_ + g) * S_ + c * CT + lane];

    const float* kkBase = g_kk + ((size_t)bh * S_ + c * CT) * E_;
    const float* vsBase = g_vs + ((size_t)bh * S_ + c * CT) * E_;
    const float* qsBase = g_qs + ((size_t)bh * S_ + c * CT) * E_;

    int b = bh >> 3, h = bh & 7;

    for (int t = 0; t < CT; t++) {
        if (tid < 64)        kkS[tid]       = kkBase[t * E_ + tid];
        else if (tid < 128)  vsS[tid - 64]  = vsBase[t * E_ + tid - 64];
        else if (tid < 192)  qsS[tid - 128] = qsBase[t * E_ + tid - 128];
        __syncthreads();

        float w = __shfl_sync(0xffffffffu, wchunk, t);
        nw  += w;
        skA += w * kkS[lane];  skB += w * kkS[lane + 32];
        svA += w * vsS[lane];  svB += w * vsS[lane + 32];

        // weights_g = qs . Sk_g / clamp(Nw_g)
        float d = qsS[lane] * skA + qsS[lane + 32] * skB;
#pragma unroll
        for (int o = 16; o; o >>= 1) d += __shfl_xor_sync(0xffffffffu, d, o);
        float nwc = fmaxf(nw, 1e-8f);
        if (lane == 0) wl[g] = d / nwc;
        __syncthreads();

        // softmax over the 16 g-values (warp 0, lanes 0..15)
        if (g == 0) {
            float x = (lane < 16) ? wl[lane] : -3.4e38f;
            float m = x;
#pragma unroll
            for (int o = 8; o; o >>= 1) m = fmaxf(m, __shfl_xor_sync(0xffffffffu, m, o));
            float e = (lane < 16) ? expf(x - m) : 0.f;
            float ss = e;
#pragma unroll
            for (int o = 8; o; o >>= 1) ss += __shfl_xor_sync(0xffffffffu, ss, o);
            if (lane < 16) pn[lane] = e / ss;
        }
        __syncthreads();

        float scale = pn[g] / nwc;
        ybuf[g][lane]      = scale * svA;
        ybuf[g][lane + 32] = scale * svB;
        __syncthreads();

        if (tid < 64) {
            float o = 0.f;
#pragma unroll
            for (int gg = 0; gg < 16; gg++) o += ybuf[gg][tid];
            g_attn[((size_t)b * S_ + c * CT + t) * DM + h * E_ + tid] = o;
        }
        __syncthreads();
    }
}

// ---------------- launch ---------------------------------------------------
extern "C" void kernel_launch(void* const* d_in, const int* in_sizes, int n_in,
                              void* d_out, int out_size)
{
    const float* q   = (const float*)d_in[0];
    const float* k   = (const float*)d_in[1];
    const float* v   = (const float*)d_in[2];
    const float* ctx = (const float*)d_in[3];
    const float* Wq  = (const float*)d_in[4];
    const float* Wk  = (const float*)d_in[5];
    const float* Wv  = (const float*)d_in[6];
    const float* Wo  = (const float*)d_in[7];
    const float* Wc  = (const float*)d_in[8];

    static float *p_qs = nullptr, *p_kk, *p_vs, *p_cs, *p_attn;
    if (!p_qs) {
        cudaGetSymbolAddress((void**)&p_qs,   g_qs);
        cudaGetSymbolAddress((void**)&p_kk,   g_kk);
        cudaGetSymbolAddress((void**)&p_vs,   g_vs);
        cudaGetSymbolAddress((void**)&p_cs,   g_cs);
        cudaGetSymbolAddress((void**)&p_attn, g_attn);
    }

    gemm512<<<dim3(1, 8),  256>>>(ctx, Wc, p_cs, B_ * G_, 1, G_);
    gemm512<<<dim3(64, 8), 256>>>(q,   Wq, p_qs, B_ * S_, 1, S_);
    gemm512<<<dim3(64, 8), 256>>>(k,   Wk, p_kk, B_ * S_, 1, S_);
    gemm512<<<dim3(64, 8), 256>>>(v,   Wv, p_vs, B_ * S_, 1, S_);

    scores_kernel<<<NCHAIN, 256>>>();
    mean_kernel<<<1, 256>>>();
    wexp_kernel<<<(NCHAIN * S_) / 256, 256>>>();
    chunk_sums_kernel<<<dim3(NCHAIN, CH), 64>>>();
    chunk_prefix_kernel<<<NCHAIN, 160>>>();
    attn_scan_kernel<<<dim3(B_ * H_, CH), 512>>>();

    gemm512<<<dim3(64, 8), 256>>>(p_attn, Wo, (float*)d_out, B_ * S_, 0, 0);
}

// round 8
// speedup vs baseline: 1.4048x; 1.4048x over previous
#include <cuda_runtime.h>
#include <cuda_bf16.h>
#include <cstdint>

#define B_   2
#define H_   8
#define G_   16
#define S_   2048
#define E_   64
#define DM   512
#define CT   32
#define CH   (S_/CT)
#define NCHAIN (B_*H_*G_)
#define REC  132
#define KCH  32
#define NCHUNK (DM/KCH)

// ---------------- fp32 scratch ----------------
__device__ float  g_qs[B_*H_*S_*E_];
__device__ float  g_kk[B_*H_*S_*E_];
__device__ float  g_vs[B_*H_*S_*E_];
__device__ float  g_cs[B_*H_*G_*E_];
__device__ float  g_scores[NCHAIN*S_];
__device__ float  g_wexp[NCHAIN*S_];
__device__ float  g_chunk[NCHAIN*CH*REC];
__device__ float  g_attn[B_*S_*DM];
__device__ double g_partial[NCHAIN];
__device__ float  g_mean;

// ---------------- bf16 hi/lo buffers (uint4 for 16B alignment) -------------
__device__ uint4 g_qh4[262144], g_ql4[262144];
__device__ uint4 g_kh4[262144], g_kl4[262144];
__device__ uint4 g_vh4[262144], g_vl4[262144];
__device__ uint4 g_ch4[2048],   g_cl4[2048];
__device__ uint4 g_wqh4[32768], g_wql4[32768];
__device__ uint4 g_wkh4[32768], g_wkl4[32768];
__device__ uint4 g_wvh4[32768], g_wvl4[32768];
__device__ uint4 g_woh4[32768], g_wol4[32768];
__device__ uint4 g_wch4[32768], g_wcl4[32768];
__device__ uint4 g_ah4[262144], g_al4[262144];

// ---------------- helpers ----------------
static __device__ __forceinline__ uint32_t pack2(float a, float b) {
    __nv_bfloat162 t = __floats2bfloat162_rn(a, b);
    return *reinterpret_cast<uint32_t*>(&t);
}
static __device__ __forceinline__ void split1(float x, float& hi, float& lo) {
    __nv_bfloat16 h = __float2bfloat16_rn(x);
    hi = __bfloat162float(h);
    lo = x - hi;
}
static __device__ __forceinline__ void mma_bf16(float* c, const uint32_t* a, const uint32_t* b) {
    asm volatile(
        "mma.sync.aligned.m16n8k16.row.col.f32.bf16.bf16.f32 "
        "{%0,%1,%2,%3}, {%4,%5,%6,%7}, {%8,%9}, {%0,%1,%2,%3};"
        : "+f"(c[0]), "+f"(c[1]), "+f"(c[2]), "+f"(c[3])
        : "r"(a[0]), "r"(a[1]), "r"(a[2]), "r"(a[3]), "r"(b[0]), "r"(b[1]));
}

// ---------------- hi/lo split pre-conversion ----------------
struct ConvSeg { const float* s; __nv_bfloat16* h; __nv_bfloat16* l; unsigned n4; };
struct Conv9 { ConvSeg seg[9]; };

__global__ __launch_bounds__(256) void convert_all(Conv9 c, unsigned total4)
{
    unsigned i = blockIdx.x * 256u + threadIdx.x;
    if (i >= total4) return;
    unsigned off = i;
#pragma unroll
    for (int s = 0; s < 9; s++) {
        unsigned n4 = c.seg[s].n4;
        if (off < n4) {
            float4 v = ((const float4*)c.seg[s].s)[off];
            float h0,h1,h2,h3,l0,l1,l2,l3;
            split1(v.x,h0,l0); split1(v.y,h1,l1); split1(v.z,h2,l2); split1(v.w,h3,l3);
            ((uint2*)c.seg[s].h)[off] = make_uint2(pack2(h0,h1), pack2(h2,h3));
            ((uint2*)c.seg[s].l)[off] = make_uint2(pack2(l0,l1), pack2(l2,l3));
            return;
        }
        off -= n4;
    }
}

__global__ __launch_bounds__(256) void convert_one(
    const float* __restrict__ s, __nv_bfloat16* __restrict__ h,
    __nv_bfloat16* __restrict__ l, unsigned n4)
{
    unsigned i = blockIdx.x * 256u + threadIdx.x;
    if (i >= n4) return;
    float4 v = ((const float4*)s)[i];
    float h0,h1,h2,h3,l0,l1,l2,l3;
    split1(v.x,h0,l0); split1(v.y,h1,l1); split1(v.z,h2,l2); split1(v.w,h3,l3);
    ((uint2*)h)[i] = make_uint2(pack2(h0,h1), pack2(h2,h3));
    ((uint2*)l)[i] = make_uint2(pack2(l0,l1), pack2(l2,l3));
}

// ================= mma.sync bf16 3-pass GEMM ===============================
// C(MxN=512) = A(MxK=512) * W(512x512); A row-major, W row-major (k,n).
// CTA 128x128, 256 thr, warp tile 64x32. K chunks of 32 staged in smem.
// mode 0: row-major out; mode 1: head-split out.
static __device__ __forceinline__ void store_pair(
    float* C, int mode, int rowsPer, int r, int cn, float x, float y, int M)
{
    if (r >= M) return;
    float2 v = make_float2(x, y);
    if (mode == 0) {
        *(float2*)&C[(size_t)r * DM + cn] = v;
    } else {
        int b = r / rowsPer, rr = r - b * rowsPer;
        int h = cn >> 6, e = cn & 63;
        *(float2*)&C[((size_t)(b * H_ + h) * rowsPer + rr) * E_ + e] = v;
    }
}

__global__ __launch_bounds__(256, 1) void mma_gemm(
    const __nv_bfloat16* __restrict__ Ah, const __nv_bfloat16* __restrict__ Al,
    const __nv_bfloat16* __restrict__ Wh, const __nv_bfloat16* __restrict__ Wl,
    float* __restrict__ C, int M, int mode, int rowsPer)
{
    __shared__ uint32_t Ash[128*20], Asl[128*20], Bsh[128*20], Bsl[128*20];

    int tid = threadIdx.x, lane = tid & 31, wid = tid >> 5;
    int g = lane >> 2, t = lane & 3;
    int wm = wid & 1, wn = wid >> 1;
    int m0 = blockIdx.x * 128, n0 = blockIdx.y * 128;

    float acc[64];
#pragma unroll
    for (int i = 0; i < 64; i++) acc[i] = 0.f;

    // A staging: thread -> (row, 16-half segment)
    int sa_m  = tid >> 1;
    int sa_k8 = (tid & 1) << 3;            // k-pair index 0 or 8
    bool sa_ok = (m0 + sa_m) < M;
    // B staging: thread -> (k-pair row, 8-col group)
    int sb_ng = tid & 15, sb_kp = tid >> 4;
    int sb_n8 = sb_ng * 8;

    uint4 pah0, pah1, pal0, pal1, pbh0, pbh1, pbl0, pbl1;
    const uint4 z4 = make_uint4(0, 0, 0, 0);

    auto prefetch = [&](int ic) {
        int hoff = ic * KCH + sa_k8 * 2;
        if (sa_ok) {
            const __nv_bfloat16* p = Ah + (size_t)(m0 + sa_m) * DM + hoff;
            pah0 = *(const uint4*)p;  pah1 = *(const uint4*)(p + 8);
            const __nv_bfloat16* q = Al + (size_t)(m0 + sa_m) * DM + hoff;
            pal0 = *(const uint4*)q;  pal1 = *(const uint4*)(q + 8);
        } else { pah0 = pah1 = pal0 = pal1 = z4; }
        int krow = ic * KCH + 2 * sb_kp;
        const __nv_bfloat16* b0 = Wh + (size_t)krow * DM + n0 + sb_n8;
        pbh0 = *(const uint4*)b0;  pbh1 = *(const uint4*)(b0 + DM);
        const __nv_bfloat16* b1 = Wl + (size_t)krow * DM + n0 + sb_n8;
        pbl0 = *(const uint4*)b1;  pbl1 = *(const uint4*)(b1 + DM);
    };

    prefetch(0);

    for (int ic = 0; ic < NCHUNK; ic++) {
        __syncthreads();
        // store staged regs to smem
        *(uint4*)&Ash[sa_m * 20 + sa_k8]     = pah0;
        *(uint4*)&Ash[sa_m * 20 + sa_k8 + 4] = pah1;
        *(uint4*)&Asl[sa_m * 20 + sa_k8]     = pal0;
        *(uint4*)&Asl[sa_m * 20 + sa_k8 + 4] = pal1;
        {
            const uint16_t* r0h = (const uint16_t*)&pbh0;
            const uint16_t* r1h = (const uint16_t*)&pbh1;
            const uint16_t* r0l = (const uint16_t*)&pbl0;
            const uint16_t* r1l = (const uint16_t*)&pbl1;
#pragma unroll
            for (int i = 0; i < 8; i++) {
                int r = (i + sb_ng) & 7;
                Bsh[(sb_n8 + r) * 20 + sb_kp] = (uint32_t)r0h[r] | ((uint32_t)r1h[r] << 16);
                Bsl[(sb_n8 + r) * 20 + sb_kp] = (uint32_t)r0l[r] | ((uint32_t)r1l[r] << 16);
            }
        }
        __syncthreads();
        if (ic + 1 < NCHUNK) prefetch(ic + 1);

        // MMA over this chunk: 2 k-steps of 16 halves (8 pairs)
#pragma unroll
        for (int ks = 0; ks < 2; ks++) {
            int k0 = ks * 8;
            uint32_t bh[4][2], bl[4][2];
#pragma unroll
            for (int j = 0; j < 4; j++) {
                int n = wn * 32 + j * 8 + g;
                bh[j][0] = Bsh[n * 20 + k0 + t];
                bh[j][1] = Bsh[n * 20 + k0 + t + 4];
                bl[j][0] = Bsl[n * 20 + k0 + t];
                bl[j][1] = Bsl[n * 20 + k0 + t + 4];
            }
#pragma unroll
            for (int i = 0; i < 4; i++) {
                int m = wm * 64 + i * 16 + g;
                uint32_t ah[4], al[4];
                ah[0] = Ash[m * 20 + k0 + t];
                ah[1] = Ash[(m + 8) * 20 + k0 + t];
                ah[2] = Ash[m * 20 + k0 + t + 4];
                ah[3] = Ash[(m + 8) * 20 + k0 + t + 4];
                al[0] = Asl[m * 20 + k0 + t];
                al[1] = Asl[(m + 8) * 20 + k0 + t];
                al[2] = Asl[m * 20 + k0 + t + 4];
                al[3] = Asl[(m + 8) * 20 + k0 + t + 4];
#pragma unroll
                for (int j = 0; j < 4; j++) mma_bf16(&acc[(i * 4 + j) * 4], ah, bh[j]);
#pragma unroll
                for (int j = 0; j < 4; j++) mma_bf16(&acc[(i * 4 + j) * 4], ah, bl[j]);
#pragma unroll
                for (int j = 0; j < 4; j++) mma_bf16(&acc[(i * 4 + j) * 4], al, bh[j]);
            }
        }
    }

    // epilogue: direct register -> global
#pragma unroll
    for (int i = 0; i < 4; i++) {
        int r = m0 + wm * 64 + i * 16 + g;
#pragma unroll
        for (int j = 0; j < 4; j++) {
            int cn = n0 + wn * 32 + j * 8 + t * 2;
            float* a4 = &acc[(i * 4 + j) * 4];
            store_pair(C, mode, rowsPer, r,     cn, a4[0], a4[1], M);
            store_pair(C, mode, rowsPer, r + 8, cn, a4[2], a4[3], M);
        }
    }
}

// ---------------- scores ----------------
__global__ __launch_bounds__(256) void scores_kernel()
{
    int chain = blockIdx.x;
    int bh = chain >> 4;
    __shared__ float csh[64];
    __shared__ double dsh[8];
    int tid = threadIdx.x, lane = tid & 31, wp = tid >> 5;
    if (tid < 64) csh[tid] = g_cs[(size_t)chain * E_ + tid];
    __syncthreads();
    double local = 0.0;
    for (int s = wp; s < S_; s += 8) {
        const float* kp = g_kk + ((size_t)bh * S_ + s) * E_;
        float d = csh[lane] * kp[lane] + csh[lane + 32] * kp[lane + 32];
#pragma unroll
        for (int o = 16; o; o >>= 1) d += __shfl_xor_sync(0xffffffffu, d, o);
        if (lane == 0) {
            d *= 0.125f;
            g_scores[(size_t)chain * S_ + s] = d;
            local += (double)d;
        }
    }
    if (lane == 0) dsh[wp] = local;
    __syncthreads();
    if (tid == 0) {
        double t = 0.0;
        for (int i = 0; i < 8; i++) t += dsh[i];
        g_partial[chain] = t;
    }
}

__global__ __launch_bounds__(256) void mean_kernel()
{
    __shared__ double sh[256];
    int t = threadIdx.x;
    sh[t] = g_partial[t];
    __syncthreads();
    for (int o = 128; o; o >>= 1) {
        if (t < o) sh[t] += sh[t + o];
        __syncthreads();
    }
    if (t == 0) g_mean = (float)(sh[0] / (double)((size_t)NCHAIN * S_));
}

__global__ __launch_bounds__(256) void wexp_kernel()
{
    int i = blockIdx.x * 256 + threadIdx.x;
    g_wexp[i] = expf(g_scores[i] - g_mean);
}

__global__ __launch_bounds__(64) void chunk_sums_kernel()
{
    int chain = blockIdx.x, c = blockIdx.y;
    int tid = threadIdx.x;
    int bh = chain >> 4;
    __shared__ float wsh[CT];
    if (tid < CT) wsh[tid] = g_wexp[(size_t)chain * S_ + c * CT + tid];
    __syncthreads();
    const float* kb = g_kk + ((size_t)bh * S_ + c * CT) * E_ + tid;
    const float* vb = g_vs + ((size_t)bh * S_ + c * CT) * E_ + tid;
    float ak = 0.f, av = 0.f;
#pragma unroll 8
    for (int t = 0; t < CT; t++) {
        float w = wsh[t];
        ak += w * kb[t * E_];
        av += w * vb[t * E_];
    }
    float* op = g_chunk + ((size_t)chain * CH + c) * REC;
    op[1 + tid] = ak;
    op[65 + tid] = av;
    if (tid == 0) {
        float s = 0.f;
        for (int t = 0; t < CT; t++) s += wsh[t];
        op[0] = s;
    }
}

__global__ __launch_bounds__(160) void chunk_prefix_kernel()
{
    int chain = blockIdx.x;
    int t = threadIdx.x;
    if (t >= 129) return;
    float run = 0.f;
    for (int c = 0; c < CH; c++) {
        size_t idx = ((size_t)chain * CH + c) * REC + t;
        float v = g_chunk[idx];
        g_chunk[idx] = run;
        run += v;
    }
}

// ---------------- fused scan: preloaded tiles, 2 barriers/step -------------
__global__ __launch_bounds__(512) void attn_scan_kernel()
{
    int bh = blockIdx.x, c = blockIdx.y;
    int tid = threadIdx.x;
    int g = tid >> 5, lane = tid & 31;

    __shared__ float kkS[CT * 64], vsS[CT * 64], qsS[CT * 64];
    __shared__ float wl[2][16];
    __shared__ float ybuf[2][16][64];

    const float* kkBase = g_kk + ((size_t)bh * S_ + c * CT) * E_;
    const float* vsBase = g_vs + ((size_t)bh * S_ + c * CT) * E_;
    const float* qsBase = g_qs + ((size_t)bh * S_ + c * CT) * E_;
    ((float4*)kkS)[tid] = ((const float4*)kkBase)[tid];
    ((float4*)vsS)[tid] = ((const float4*)vsBase)[tid];
    ((float4*)qsS)[tid] = ((const float4*)qsBase)[tid];

    const float* pf = g_chunk + ((size_t)(bh * G_ + g) * CH + c) * REC;
    float nw  = pf[0];
    float skA = pf[1 + lane];
    float skB = pf[1 + 32 + lane];
    float svA = pf[65 + lane];
    float svB = pf[65 + 32 + lane];
    float wchunk = g_wexp[(size_t)(bh * G_ + g) * S_ + c * CT + lane];

    int b = bh >> 3, h = bh & 7;
    float* outBase = g_attn + ((size_t)b * S_ + c * CT) * DM + h * E_;
    __syncthreads();

    for (int t = 0; t < CT; t++) {
        int p = t & 1;
        float w = __shfl_sync(0xffffffffu, wchunk, t);
        nw  += w;
        skA += w * kkS[t * 64 + lane];  skB += w * kkS[t * 64 + lane + 32];
        svA += w * vsS[t * 64 + lane];  svB += w * vsS[t * 64 + lane + 32];

        float d = qsS[t * 64 + lane] * skA + qsS[t * 64 + lane + 32] * skB;
#pragma unroll
        for (int o = 16; o; o >>= 1) d += __shfl_xor_sync(0xffffffffu, d, o);
        float nwc = fmaxf(nw, 1e-8f);
        if (lane == 0) wl[p][g] = d / nwc;
        __syncthreads();

        float x = (lane < 16) ? wl[p][lane] : -1e30f;
        float m = x;
#pragma unroll
        for (int o = 16; o; o >>= 1) m = fmaxf(m, __shfl_xor_sync(0xffffffffu, m, o));
        float e = (lane < 16) ? expf(x - m) : 0.f;
        float ss = e;
#pragma unroll
        for (int o = 16; o; o >>= 1) ss += __shfl_xor_sync(0xffffffffu, ss, o);
        float eg = __shfl_sync(0xffffffffu, e, g);
        float scale = (eg / ss) / nwc;

        ybuf[p][g][lane]      = scale * svA;
        ybuf[p][g][lane + 32] = scale * svB;
        __syncthreads();

        if (tid < 64) {
            float o = 0.f;
#pragma unroll
            for (int gg = 0; gg < 16; gg++) o += ybuf[p][gg][tid];
            outBase[(size_t)t * DM + tid] = o;
        }
    }
}

// ---------------- launch ---------------------------------------------------
extern "C" void kernel_launch(void* const* d_in, const int* in_sizes, int n_in,
                              void* d_out, int out_size)
{
    const float* q   = (const float*)d_in[0];
    const float* k   = (const float*)d_in[1];
    const float* v   = (const float*)d_in[2];
    const float* ctx = (const float*)d_in[3];

    typedef __nv_bfloat16 bf;
    static float *p_qs = nullptr, *p_kk, *p_vs, *p_cs, *p_attn;
    static bf *qh,*ql,*kh,*kl,*vh,*vl,*ch,*cl;
    static bf *wqh,*wql,*wkh,*wkl,*wvh,*wvl,*woh,*wol,*wch,*wcl;
    static bf *ah,*al;
    if (!p_qs) {
        cudaGetSymbolAddress((void**)&p_qs,   g_qs);
        cudaGetSymbolAddress((void**)&p_kk,   g_kk);
        cudaGetSymbolAddress((void**)&p_vs,   g_vs);
        cudaGetSymbolAddress((void**)&p_cs,   g_cs);
        cudaGetSymbolAddress((void**)&p_attn, g_attn);
        cudaGetSymbolAddress((void**)&qh, g_qh4);  cudaGetSymbolAddress((void**)&ql, g_ql4);
        cudaGetSymbolAddress((void**)&kh, g_kh4);  cudaGetSymbolAddress((void**)&kl, g_kl4);
        cudaGetSymbolAddress((void**)&vh, g_vh4);  cudaGetSymbolAddress((void**)&vl, g_vl4);
        cudaGetSymbolAddress((void**)&ch, g_ch4);  cudaGetSymbolAddress((void**)&cl, g_cl4);
        cudaGetSymbolAddress((void**)&wqh, g_wqh4); cudaGetSymbolAddress((void**)&wql, g_wql4);
        cudaGetSymbolAddress((void**)&wkh, g_wkh4); cudaGetSymbolAddress((void**)&wkl, g_wkl4);
        cudaGetSymbolAddress((void**)&wvh, g_wvh4); cudaGetSymbolAddress((void**)&wvl, g_wvl4);
        cudaGetSymbolAddress((void**)&woh, g_woh4); cudaGetSymbolAddress((void**)&wol, g_wol4);
        cudaGetSymbolAddress((void**)&wch, g_wch4); cudaGetSymbolAddress((void**)&wcl, g_wcl4);
        cudaGetSymbolAddress((void**)&ah, g_ah4);   cudaGetSymbolAddress((void**)&al, g_al4);
    }

    const unsigned N_BIG = (B_*S_*DM)/4;     // 524288
    const unsigned N_CTX = (B_*G_*DM)/4;     // 4096
    const unsigned N_W   = (DM*DM)/4;        // 65536

    Conv9 c9;
    c9.seg[0] = { q,                     qh,  ql,  N_BIG };
    c9.seg[1] = { k,                     kh,  kl,  N_BIG };
    c9.seg[2] = { v,                     vh,  vl,  N_BIG };
    c9.seg[3] = { ctx,                   ch,  cl,  N_CTX };
    c9.seg[4] = { (const float*)d_in[4], wqh, wql, N_W };
    c9.seg[5] = { (const float*)d_in[5], wkh, wkl, N_W };
    c9.seg[6] = { (const float*)d_in[6], wvh, wvl, N_W };
    c9.seg[7] = { (const float*)d_in[7], woh, wol, N_W };
    c9.seg[8] = { (const float*)d_in[8], wch, wcl, N_W };
    unsigned total4 = 3 * N_BIG + N_CTX + 5 * N_W;

    convert_all<<<(total4 + 255) / 256, 256>>>(c9, total4);

    mma_gemm<<<dim3(1, 4),  256>>>(ch, cl, wch, wcl, p_cs, B_ * G_, 1, G_);
    mma_gemm<<<dim3(32, 4), 256>>>(qh, ql, wqh, wql, p_qs, B_ * S_, 1, S_);
    mma_gemm<<<dim3(32, 4), 256>>>(kh, kl, wkh, wkl, p_kk, B_ * S_, 1, S_);
    mma_gemm<<<dim3(32, 4), 256>>>(vh, vl, wvh, wvl, p_vs, B_ * S_, 1, S_);

    scores_kernel<<<NCHAIN, 256>>>();
    mean_kernel<<<1, 256>>>();
    wexp_kernel<<<(NCHAIN * S_) / 256, 256>>>();
    chunk_sums_kernel<<<dim3(NCHAIN, CH), 64>>>();
    chunk_prefix_kernel<<<NCHAIN, 160>>>();
    attn_scan_kernel<<<dim3(B_ * H_, CH), 512>>>();

    convert_one<<<N_BIG / 256, 256>>>(p_attn, ah, al, N_BIG);
    mma_gemm<<<dim3(32, 4), 256>>>(ah, al, woh, wol, (float*)d_out, B_ * S_, 0, 0);
}

// round 9
// speedup vs baseline: 1.9300x; 1.3739x over previous
#include <cuda_runtime.h>
#include <cuda_bf16.h>
#include <cstdint>

#define B_   2
#define H_   8
#define G_   16
#define S_   2048
#define E_   64
#define DM   512
#define CT   32
#define CH   (S_/CT)
#define NCHAIN (B_*H_*G_)
#define REC  132
#define KCH  32
#define NCHUNK (DM/KCH)

// ---------------- fp32 scratch ----------------
__device__ float  g_qs[B_*H_*S_*E_];
__device__ float  g_kk[B_*H_*S_*E_];
__device__ float  g_vs[B_*H_*S_*E_];
__device__ float  g_cs[B_*H_*G_*E_];
__device__ float  g_scores[NCHAIN*S_];
__device__ float  g_wexp[NCHAIN*S_];
__device__ float  g_chunk[NCHAIN*CH*REC];
__device__ float  g_attn[B_*S_*DM];
__device__ double g_partial[256];
__device__ float  g_mean;

// ---------------- bf16 hi/lo buffers ----------------
__device__ uint4 g_qh4[262144], g_ql4[262144];
__device__ uint4 g_kh4[262144], g_kl4[262144];
__device__ uint4 g_vh4[262144], g_vl4[262144];
__device__ uint4 g_ch4[2048],   g_cl4[2048];
__device__ uint4 g_wqh4[32768], g_wql4[32768];
__device__ uint4 g_wkh4[32768], g_wkl4[32768];
__device__ uint4 g_wvh4[32768], g_wvl4[32768];
__device__ uint4 g_woh4[32768], g_wol4[32768];
__device__ uint4 g_wch4[32768], g_wcl4[32768];
__device__ uint4 g_ah4[262144], g_al4[262144];

// ---------------- helpers ----------------
static __device__ __forceinline__ uint32_t pack2(float a, float b) {
    __nv_bfloat162 t = __floats2bfloat162_rn(a, b);
    return *reinterpret_cast<uint32_t*>(&t);
}
static __device__ __forceinline__ void split1(float x, float& hi, float& lo) {
    __nv_bfloat16 h = __float2bfloat16_rn(x);
    hi = __bfloat162float(h);
    lo = x - hi;
}
static __device__ __forceinline__ void mma_bf16(float* c, const uint32_t* a, const uint32_t* b) {
    asm volatile(
        "mma.sync.aligned.m16n8k16.row.col.f32.bf16.bf16.f32 "
        "{%0,%1,%2,%3}, {%4,%5,%6,%7}, {%8,%9}, {%0,%1,%2,%3};"
        : "+f"(c[0]), "+f"(c[1]), "+f"(c[2]), "+f"(c[3])
        : "r"(a[0]), "r"(a[1]), "r"(a[2]), "r"(a[3]), "r"(b[0]), "r"(b[1]));
}
static __device__ __forceinline__ uint32_t smem_u32(const void* p) {
    uint32_t a;
    asm("{ .reg .u64 t; cvta.to.shared.u64 t, %1; cvt.u32.u64 %0, t; }" : "=r"(a) : "l"(p));
    return a;
}
static __device__ __forceinline__ void cpasync16(uint32_t dst, const void* src) {
    asm volatile("cp.async.cg.shared.global [%0], [%1], 16;" :: "r"(dst), "l"(src));
}
#define CP_COMMIT() asm volatile("cp.async.commit_group;" ::: "memory")
#define CP_WAIT0()  asm volatile("cp.async.wait_group 0;" ::: "memory")

// ---------------- hi/lo split pre-conversion ----------------
struct ConvSeg { const float* s; __nv_bfloat16* h; __nv_bfloat16* l; unsigned n4; };
struct Conv9 { ConvSeg seg[9]; };

__global__ __launch_bounds__(256) void convert_all(Conv9 c, unsigned total4)
{
    unsigned i = blockIdx.x * 256u + threadIdx.x;
    if (i >= total4) return;
    unsigned off = i;
#pragma unroll
    for (int s = 0; s < 9; s++) {
        unsigned n4 = c.seg[s].n4;
        if (off < n4) {
            float4 v = ((const float4*)c.seg[s].s)[off];
            float h0,h1,h2,h3,l0,l1,l2,l3;
            split1(v.x,h0,l0); split1(v.y,h1,l1); split1(v.z,h2,l2); split1(v.w,h3,l3);
            ((uint2*)c.seg[s].h)[off] = make_uint2(pack2(h0,h1), pack2(h2,h3));
            ((uint2*)c.seg[s].l)[off] = make_uint2(pack2(l0,l1), pack2(l2,l3));
            return;
        }
        off -= n4;
    }
}

__global__ __launch_bounds__(256) void convert_one(
    const float* __restrict__ s, __nv_bfloat16* __restrict__ h,
    __nv_bfloat16* __restrict__ l, unsigned n4)
{
    unsigned i = blockIdx.x * 256u + threadIdx.x;
    if (i >= n4) return;
    float4 v = ((const float4*)s)[i];
    float h0,h1,h2,h3,l0,l1,l2,l3;
    split1(v.x,h0,l0); split1(v.y,h1,l1); split1(v.z,h2,l2); split1(v.w,h3,l3);
    ((uint2*)h)[i] = make_uint2(pack2(h0,h1), pack2(h2,h3));
    ((uint2*)l)[i] = make_uint2(pack2(l0,l1), pack2(l2,l3));
}

// ================= mma.sync bf16 3-pass GEMM v2 ============================
// 512 threads, 16 warps (4x4), warp tile 32x32, CTA 128x128.
// A staged via cp.async (threads 0-255), B pair-transposed via regs (256-511).
// Double-buffered smem.
#define GSTRIDE 20
#define AWORDS  (128*GSTRIDE)          /* 2560 words per array */
#define STAGEW  (4*AWORDS)             /* 10240 words = 40KB per stage */
#define GSMEM_BYTES (2*STAGEW*4)       /* 81920 */

static __device__ __forceinline__ void store_pair(
    float* C, int mode, int rowsPer, int r, int cn, float x, float y, int M)
{
    if (r >= M) return;
    float2 v = make_float2(x, y);
    if (mode == 0) {
        *(float2*)&C[(size_t)r * DM + cn] = v;
    } else {
        int b = r / rowsPer, rr = r - b * rowsPer;
        int h = cn >> 6, e = cn & 63;
        *(float2*)&C[((size_t)(b * H_ + h) * rowsPer + rr) * E_ + e] = v;
    }
}

__global__ __launch_bounds__(512, 1) void mma_gemm(
    const __nv_bfloat16* __restrict__ Ah, const __nv_bfloat16* __restrict__ Al,
    const __nv_bfloat16* __restrict__ Wh, const __nv_bfloat16* __restrict__ Wl,
    float* __restrict__ C, int M, int mode, int rowsPer)
{
    extern __shared__ uint32_t smw[];
    int tid = threadIdx.x, lane = tid & 31, wid = tid >> 5;
    int g = lane >> 2, t = lane & 3;
    int wm = wid & 3, wn = wid >> 2;
    int m0 = blockIdx.x * 128, n0 = blockIdx.y * 128;

    float acc[2][4][4];
#pragma unroll
    for (int i = 0; i < 2; i++)
#pragma unroll
        for (int j = 0; j < 4; j++)
#pragma unroll
            for (int q = 0; q < 4; q++) acc[i][j][q] = 0.f;

    // A copier mapping (tid < 256)
    int sa_m = tid >> 1, sa_half = tid & 1;
    int sa_mc = (m0 + sa_m < M) ? sa_m : (M - 1 - m0 > 0 ? M - 1 - m0 : 0);
    // B copier mapping (tid >= 256)
    int u = tid - 256;
    int sb_ng = u & 15, sb_kp = u >> 4;
    int sb_n8 = sb_ng * 8;

    uint32_t smb = smem_u32(smw);
    uint4 pbh0, pbh1, pbl0, pbl1;

    auto issueA = [&](int ic, int stage) {
        const __nv_bfloat16* ph = Ah + (size_t)(m0 + sa_mc) * DM + ic * KCH + sa_half * 16;
        const __nv_bfloat16* pl = Al + (size_t)(m0 + sa_mc) * DM + ic * KCH + sa_half * 16;
        uint32_t wh = stage * STAGEW + sa_m * GSTRIDE + sa_half * 8;
        uint32_t wll = stage * STAGEW + AWORDS + sa_m * GSTRIDE + sa_half * 8;
        cpasync16(smb + wh * 4, ph);
        cpasync16(smb + (wh + 4) * 4, ph + 8);
        cpasync16(smb + wll * 4, pl);
        cpasync16(smb + (wll + 4) * 4, pl + 8);
    };
    auto loadB = [&](int ic) {
        int krow = ic * KCH + 2 * sb_kp;
        const __nv_bfloat16* b0 = Wh + (size_t)krow * DM + n0 + sb_n8;
        pbh0 = *(const uint4*)b0;  pbh1 = *(const uint4*)(b0 + DM);
        const __nv_bfloat16* b1 = Wl + (size_t)krow * DM + n0 + sb_n8;
        pbl0 = *(const uint4*)b1;  pbl1 = *(const uint4*)(b1 + DM);
    };
    auto storeB = [&](int stage) {
        uint32_t* Bsh = smw + stage * STAGEW + 2 * AWORDS;
        uint32_t* Bsl = Bsh + AWORDS;
        const uint16_t* r0h = (const uint16_t*)&pbh0;
        const uint16_t* r1h = (const uint16_t*)&pbh1;
        const uint16_t* r0l = (const uint16_t*)&pbl0;
        const uint16_t* r1l = (const uint16_t*)&pbl1;
#pragma unroll
        for (int i = 0; i < 8; i++) {
            int r = (i + sb_ng) & 7;
            Bsh[(sb_n8 + r) * GSTRIDE + sb_kp] = (uint32_t)r0h[r] | ((uint32_t)r1h[r] << 16);
            Bsl[(sb_n8 + r) * GSTRIDE + sb_kp] = (uint32_t)r0l[r] | ((uint32_t)r1l[r] << 16);
        }
    };

    // prologue
    if (tid < 256) issueA(0, 0); else loadB(0);
    CP_COMMIT();

    for (int ic = 0; ic < NCHUNK; ic++) {
        int buf = ic & 1;
        CP_WAIT0();
        if (tid >= 256) storeB(buf);
        __syncthreads();
        if (ic + 1 < NCHUNK) {
            if (tid < 256) issueA(ic + 1, buf ^ 1); else loadB(ic + 1);
        }
        CP_COMMIT();

        const uint32_t* Ash = smw + buf * STAGEW;
        const uint32_t* Asl = Ash + AWORDS;
        const uint32_t* Bsh = Ash + 2 * AWORDS;
        const uint32_t* Bsl = Ash + 3 * AWORDS;

#pragma unroll
        for (int ks = 0; ks < 2; ks++) {
            int k0 = ks * 8;
            uint32_t bh[4][2], bl[4][2];
#pragma unroll
            for (int j = 0; j < 4; j++) {
                int n = wn * 32 + j * 8 + g;
                bh[j][0] = Bsh[n * GSTRIDE + k0 + t];
                bh[j][1] = Bsh[n * GSTRIDE + k0 + t + 4];
                bl[j][0] = Bsl[n * GSTRIDE + k0 + t];
                bl[j][1] = Bsl[n * GSTRIDE + k0 + t + 4];
            }
#pragma unroll
            for (int i = 0; i < 2; i++) {
                int m = wm * 32 + i * 16 + g;
                uint32_t ah[4], al[4];
                ah[0] = Ash[m * GSTRIDE + k0 + t];
                ah[1] = Ash[(m + 8) * GSTRIDE + k0 + t];
                ah[2] = Ash[m * GSTRIDE + k0 + t + 4];
                ah[3] = Ash[(m + 8) * GSTRIDE + k0 + t + 4];
                al[0] = Asl[m * GSTRIDE + k0 + t];
                al[1] = Asl[(m + 8) * GSTRIDE + k0 + t];
                al[2] = Asl[m * GSTRIDE + k0 + t + 4];
                al[3] = Asl[(m + 8) * GSTRIDE + k0 + t + 4];
#pragma unroll
                for (int j = 0; j < 4; j++) mma_bf16(acc[i][j], ah, bh[j]);
#pragma unroll
                for (int j = 0; j < 4; j++) mma_bf16(acc[i][j], ah, bl[j]);
#pragma unroll
                for (int j = 0; j < 4; j++) mma_bf16(acc[i][j], al, bh[j]);
            }
        }
    }

#pragma unroll
    for (int i = 0; i < 2; i++) {
        int r = m0 + wm * 32 + i * 16 + g;
#pragma unroll
        for (int j = 0; j < 4; j++) {
            int cn = n0 + wn * 32 + j * 8 + t * 2;
            store_pair(C, mode, rowsPer, r,     cn, acc[i][j][0], acc[i][j][1], M);
            store_pair(C, mode, rowsPer, r + 8, cn, acc[i][j][2], acc[i][j][3], M);
        }
    }
}

// ---------------- scores v2: block=(bh, s-tile 256), kk in regs ------------
__global__ __launch_bounds__(256) void scores_kernel()
{
    int bh = blockIdx.x, stile = blockIdx.y;
    int tid = threadIdx.x;
    int s = stile * 256 + tid;

    __shared__ float csS[G_ * 64];
    ((float4*)csS)[tid] = ((const float4*)(g_cs + (size_t)bh * G_ * 64))[tid];
    __syncthreads();

    float kkr[64];
    const float4* kp = (const float4*)(g_kk + ((size_t)bh * S_ + s) * 64);
#pragma unroll
    for (int i = 0; i < 16; i++) {
        float4 v = kp[i];
        kkr[i*4] = v.x; kkr[i*4+1] = v.y; kkr[i*4+2] = v.z; kkr[i*4+3] = v.w;
    }

    double local = 0.0;
#pragma unroll
    for (int g = 0; g < G_; g++) {
        float d = 0.f;
#pragma unroll
        for (int e = 0; e < 64; e++) d += csS[g * 64 + e] * kkr[e];
        d *= 0.125f;
        g_scores[((size_t)(bh * G_ + g)) * S_ + s] = d;
        local += (double)d;
    }

    __shared__ double sh[256];
    sh[tid] = local;
    __syncthreads();
    for (int o = 128; o; o >>= 1) {
        if (tid < o) sh[tid] += sh[tid + o];
        __syncthreads();
    }
    if (tid == 0) g_partial[stile * G_ + bh] = sh[0];
}

__global__ __launch_bounds__(128) void mean_kernel()
{
    __shared__ double sh[128];
    int t = threadIdx.x;
    sh[t] = g_partial[t];
    __syncthreads();
    for (int o = 64; o; o >>= 1) {
        if (t < o) sh[t] += sh[t + o];
        __syncthreads();
    }
    if (t == 0) g_mean = (float)(sh[0] / (double)((size_t)NCHAIN * S_));
}

__global__ __launch_bounds__(256) void wexp_kernel()
{
    int i = blockIdx.x * 256 + threadIdx.x;
    g_wexp[i] = expf(g_scores[i] - g_mean);
}

// ---------------- chunk sums v2: block=(bh,chunk), shared kk/vs tile -------
__global__ __launch_bounds__(512) void chunk_sums_kernel()
{
    int bh = blockIdx.x, c = blockIdx.y;
    int tid = threadIdx.x;
    int g = tid >> 5, lane = tid & 31;

    __shared__ float kkS[CT * 64], vsS[CT * 64];
    ((float4*)kkS)[tid] = ((const float4*)(g_kk + ((size_t)bh * S_ + c * CT) * 64))[tid];
    ((float4*)vsS)[tid] = ((const float4*)(g_vs + ((size_t)bh * S_ + c * CT) * 64))[tid];

    int chain = bh * G_ + g;
    float wreg = g_wexp[(size_t)chain * S_ + c * CT + lane];
    __syncthreads();

    float nw = 0.f, ak0 = 0.f, ak1 = 0.f, av0 = 0.f, av1 = 0.f;
#pragma unroll
    for (int t = 0; t < CT; t++) {
        float w = __shfl_sync(0xffffffffu, wreg, t);
        nw += w;
        ak0 += w * kkS[t * 64 + lane];
        ak1 += w * kkS[t * 64 + lane + 32];
        av0 += w * vsS[t * 64 + lane];
        av1 += w * vsS[t * 64 + lane + 32];
    }
    float* op = g_chunk + ((size_t)chain * CH + c) * REC;
    op[1 + lane]  = ak0;
    op[33 + lane] = ak1;
    op[65 + lane] = av0;
    op[97 + lane] = av1;
    if (lane == 0) op[0] = nw;
}

__global__ __launch_bounds__(160) void chunk_prefix_kernel()
{
    int chain = blockIdx.x;
    int t = threadIdx.x;
    if (t >= 129) return;
    float run = 0.f;
    for (int c = 0; c < CH; c++) {
        size_t idx = ((size_t)chain * CH + c) * REC + t;
        float v = g_chunk[idx];
        g_chunk[idx] = run;
        run += v;
    }
}

// ---------------- fused scan ----------------
__global__ __launch_bounds__(512) void attn_scan_kernel()
{
    int bh = blockIdx.x, c = blockIdx.y;
    int tid = threadIdx.x;
    int g = tid >> 5, lane = tid & 31;

    __shared__ float kkS[CT * 64], vsS[CT * 64], qsS[CT * 64];
    __shared__ float wl[2][16];
    __shared__ float ybuf[2][16][64];

    const float* kkBase = g_kk + ((size_t)bh * S_ + c * CT) * E_;
    const float* vsBase = g_vs + ((size_t)bh * S_ + c * CT) * E_;
    const float* qsBase = g_qs + ((size_t)bh * S_ + c * CT) * E_;
    ((float4*)kkS)[tid] = ((const float4*)kkBase)[tid];
    ((float4*)vsS)[tid] = ((const float4*)vsBase)[tid];
    ((float4*)qsS)[tid] = ((const float4*)qsBase)[tid];

    const float* pf = g_chunk + ((size_t)(bh * G_ + g) * CH + c) * REC;
    float nw  = pf[0];
    float skA = pf[1 + lane];
    float skB = pf[1 + 32 + lane];
    float svA = pf[65 + lane];
    float svB = pf[65 + 32 + lane];
    float wchunk = g_wexp[(size_t)(bh * G_ + g) * S_ + c * CT + lane];

    int b = bh >> 3, h = bh & 7;
    float* outBase = g_attn + ((size_t)b * S_ + c * CT) * DM + h * E_;
    __syncthreads();

    for (int t = 0; t < CT; t++) {
        int p = t & 1;
        float w = __shfl_sync(0xffffffffu, wchunk, t);
        nw  += w;
        skA += w * kkS[t * 64 + lane];  skB += w * kkS[t * 64 + lane + 32];
        svA += w * vsS[t * 64 + lane];  svB += w * vsS[t * 64 + lane + 32];

        float d = qsS[t * 64 + lane] * skA + qsS[t * 64 + lane + 32] * skB;
#pragma unroll
        for (int o = 16; o; o >>= 1) d += __shfl_xor_sync(0xffffffffu, d, o);
        float nwc = fmaxf(nw, 1e-8f);
        if (lane == 0) wl[p][g] = d / nwc;
        __syncthreads();

        float x = (lane < 16) ? wl[p][lane] : -1e30f;
        float m = x;
#pragma unroll
        for (int o = 16; o; o >>= 1) m = fmaxf(m, __shfl_xor_sync(0xffffffffu, m, o));
        float e = (lane < 16) ? expf(x - m) : 0.f;
        float ss = e;
#pragma unroll
        for (int o = 16; o; o >>= 1) ss += __shfl_xor_sync(0xffffffffu, ss, o);
        float eg = __shfl_sync(0xffffffffu, e, g);
        float scale = (eg / ss) / nwc;

        ybuf[p][g][lane]      = scale * svA;
        ybuf[p][g][lane + 32] = scale * svB;
        __syncthreads();

        if (tid < 64) {
            float o = 0.f;
#pragma unroll
            for (int gg = 0; gg < 16; gg++) o += ybuf[p][gg][tid];
            outBase[(size_t)t * DM + tid] = o;
        }
    }
}

// ---------------- launch ---------------------------------------------------
extern "C" void kernel_launch(void* const* d_in, const int* in_sizes, int n_in,
                              void* d_out, int out_size)
{
    const float* q   = (const float*)d_in[0];
    const float* k   = (const float*)d_in[1];
    const float* v   = (const float*)d_in[2];
    const float* ctx = (const float*)d_in[3];

    typedef __nv_bfloat16 bf;
    static float *p_qs = nullptr, *p_kk, *p_vs, *p_cs, *p_attn;
    static bf *qh,*ql,*kh,*kl,*vh,*vl,*ch,*cl;
    static bf *wqh,*wql,*wkh,*wkl,*wvh,*wvl,*woh,*wol,*wch,*wcl;
    static bf *ah,*al;
    if (!p_qs) {
        cudaGetSymbolAddress((void**)&p_qs,   g_qs);
        cudaGetSymbolAddress((void**)&p_kk,   g_kk);
        cudaGetSymbolAddress((void**)&p_vs,   g_vs);
        cudaGetSymbolAddress((void**)&p_cs,   g_cs);
        cudaGetSymbolAddress((void**)&p_attn, g_attn);
        cudaGetSymbolAddress((void**)&qh, g_qh4);  cudaGetSymbolAddress((void**)&ql, g_ql4);
        cudaGetSymbolAddress((void**)&kh, g_kh4);  cudaGetSymbolAddress((void**)&kl, g_kl4);
        cudaGetSymbolAddress((void**)&vh, g_vh4);  cudaGetSymbolAddress((void**)&vl, g_vl4);
        cudaGetSymbolAddress((void**)&ch, g_ch4);  cudaGetSymbolAddress((void**)&cl, g_cl4);
        cudaGetSymbolAddress((void**)&wqh, g_wqh4); cudaGetSymbolAddress((void**)&wql, g_wql4);
        cudaGetSymbolAddress((void**)&wkh, g_wkh4); cudaGetSymbolAddress((void**)&wkl, g_wkl4);
        cudaGetSymbolAddress((void**)&wvh, g_wvh4); cudaGetSymbolAddress((void**)&wvl, g_wvl4);
        cudaGetSymbolAddress((void**)&woh, g_woh4); cudaGetSymbolAddress((void**)&wol, g_wol4);
        cudaGetSymbolAddress((void**)&wch, g_wch4); cudaGetSymbolAddress((void**)&wcl, g_wcl4);
        cudaGetSymbolAddress((void**)&ah, g_ah4);   cudaGetSymbolAddress((void**)&al, g_al4);
        cudaFuncSetAttribute(mma_gemm, cudaFuncAttributeMaxDynamicSharedMemorySize, GSMEM_BYTES);
    }

    const unsigned N_BIG = (B_*S_*DM)/4;
    const unsigned N_CTX = (B_*G_*DM)/4;
    const unsigned N_W   = (DM*DM)/4;

    Conv9 c9;
    c9.seg[0] = { q,                     qh,  ql,  N_BIG };
    c9.seg[1] = { k,                     kh,  kl,  N_BIG };
    c9.seg[2] = { v,                     vh,  vl,  N_BIG };
    c9.seg[3] = { ctx,                   ch,  cl,  N_CTX };
    c9.seg[4] = { (const float*)d_in[4], wqh, wql, N_W };
    c9.seg[5] = { (const float*)d_in[5], wkh, wkl, N_W };
    c9.seg[6] = { (const float*)d_in[6], wvh, wvl, N_W };
    c9.seg[7] = { (const float*)d_in[7], woh, wol, N_W };
    c9.seg[8] = { (const float*)d_in[8], wch, wcl, N_W };
    unsigned total4 = 3 * N_BIG + N_CTX + 5 * N_W;

    convert_all<<<(total4 + 255) / 256, 256>>>(c9, total4);

    mma_gemm<<<dim3(1, 4),  512, GSMEM_BYTES>>>(ch, cl, wch, wcl, p_cs, B_ * G_, 1, G_);
    mma_gemm<<<dim3(32, 4), 512, GSMEM_BYTES>>>(qh, ql, wqh, wql, p_qs, B_ * S_, 1, S_);
    mma_gemm<<<dim3(32, 4), 512, GSMEM_BYTES>>>(kh, kl, wkh, wkl, p_kk, B_ * S_, 1, S_);
    mma_gemm<<<dim3(32, 4), 512, GSMEM_BYTES>>>(vh, vl, wvh, wvl, p_vs, B_ * S_, 1, S_);

    scores_kernel<<<dim3(G_, 8), 256>>>();
    mean_kernel<<<1, 128>>>();
    wexp_kernel<<<(NCHAIN * S_) / 256, 256>>>();
    chunk_sums_kernel<<<dim3(G_, CH), 512>>>();
    chunk_prefix_kernel<<<NCHAIN, 160>>>();
    attn_scan_kernel<<<dim3(B_ * H_, CH), 512>>>();

    convert_one<<<N_BIG / 256, 256>>>(p_attn, ah, al, N_BIG);
    mma_gemm<<<dim3(32, 4), 512, GSMEM_BYTES>>>(ah, al, woh, wol, (float*)d_out, B_ * S_, 0, 0);
}

// round 10
// speedup vs baseline: 1.9327x; 1.0014x over previous
#include <cuda_runtime.h>
#include <cuda_bf16.h>
#include <cstdint>

#define B_   2
#define H_   8
#define G_   16
#define S_   2048
#define E_   64
#define DM   512
#define CT   32
#define CH   (S_/CT)
#define NCHAIN (B_*H_*G_)
#define REC  132
#define KCH  32
#define NCHUNK (DM/KCH)

// ---------------- fp32 scratch ----------------
__device__ float  g_qs[B_*H_*S_*E_];
__device__ float  g_kk[B_*H_*S_*E_];
__device__ float  g_vs[B_*H_*S_*E_];
__device__ float  g_cs[B_*H_*G_*E_];
__device__ float  g_scores[NCHAIN*S_];
__device__ float  g_wexp[NCHAIN*S_];
__device__ float  g_chunk[NCHAIN*CH*REC];
__device__ float  g_attn[B_*S_*DM];
__device__ double g_partial[256];
__device__ float  g_mean;

// ---------------- bf16 hi/lo buffers ----------------
__device__ uint4 g_qh4[262144], g_ql4[262144];
__device__ uint4 g_kh4[262144], g_kl4[262144];
__device__ uint4 g_vh4[262144], g_vl4[262144];
__device__ uint4 g_ch4[2048],   g_cl4[2048];
// transposed (n-major) weights
__device__ uint4 g_wqh4[32768], g_wql4[32768];
__device__ uint4 g_wkh4[32768], g_wkl4[32768];
__device__ uint4 g_wvh4[32768], g_wvl4[32768];
__device__ uint4 g_woh4[32768], g_wol4[32768];
__device__ uint4 g_wch4[32768], g_wcl4[32768];
__device__ uint4 g_ah4[262144], g_al4[262144];

// ---------------- helpers ----------------
static __device__ __forceinline__ uint32_t pack2(float a, float b) {
    __nv_bfloat162 t = __floats2bfloat162_rn(a, b);
    return *reinterpret_cast<uint32_t*>(&t);
}
static __device__ __forceinline__ void split1(float x, float& hi, float& lo) {
    __nv_bfloat16 h = __float2bfloat16_rn(x);
    hi = __bfloat162float(h);
    lo = x - hi;
}
static __device__ __forceinline__ void mma_bf16(float* c, const uint32_t* a, const uint32_t* b) {
    asm volatile(
        "mma.sync.aligned.m16n8k16.row.col.f32.bf16.bf16.f32 "
        "{%0,%1,%2,%3}, {%4,%5,%6,%7}, {%8,%9}, {%0,%1,%2,%3};"
        : "+f"(c[0]), "+f"(c[1]), "+f"(c[2]), "+f"(c[3])
        : "r"(a[0]), "r"(a[1]), "r"(a[2]), "r"(a[3]), "r"(b[0]), "r"(b[1]));
}
static __device__ __forceinline__ uint32_t smem_u32(const void* p) {
    uint32_t a;
    asm("{ .reg .u64 t; cvta.to.shared.u64 t, %1; cvt.u32.u64 %0, t; }" : "=r"(a) : "l"(p));
    return a;
}
static __device__ __forceinline__ void cpasync16(uint32_t dst, const void* src) {
    asm volatile("cp.async.cg.shared.global [%0], [%1], 16;" :: "r"(dst), "l"(src));
}
#define CP_COMMIT() asm volatile("cp.async.commit_group;" ::: "memory")
#define CP_WAIT1()  asm volatile("cp.async.wait_group 1;" ::: "memory")
static __device__ __forceinline__ void ldsm4(uint32_t* r, uint32_t addr) {
    asm volatile("ldmatrix.sync.aligned.m8n8.x4.shared.b16 {%0,%1,%2,%3}, [%4];"
        : "=r"(r[0]), "=r"(r[1]), "=r"(r[2]), "=r"(r[3]) : "r"(addr));
}

// ---------------- activation hi/lo split (straight layout) -----------------
struct ConvSeg { const float* s; __nv_bfloat16* h; __nv_bfloat16* l; unsigned n4; };
struct Conv4 { ConvSeg seg[4]; };

__global__ __launch_bounds__(256) void convert_act(Conv4 c, unsigned total4)
{
    unsigned i = blockIdx.x * 256u + threadIdx.x;
    if (i >= total4) return;
    unsigned off = i;
#pragma unroll
    for (int s = 0; s < 4; s++) {
        unsigned n4 = c.seg[s].n4;
        if (off < n4) {
            float4 v = ((const float4*)c.seg[s].s)[off];
            float h0,h1,h2,h3,l0,l1,l2,l3;
            split1(v.x,h0,l0); split1(v.y,h1,l1); split1(v.z,h2,l2); split1(v.w,h3,l3);
            ((uint2*)c.seg[s].h)[off] = make_uint2(pack2(h0,h1), pack2(h2,h3));
            ((uint2*)c.seg[s].l)[off] = make_uint2(pack2(l0,l1), pack2(l2,l3));
            return;
        }
        off -= n4;
    }
}

__global__ __launch_bounds__(256) void convert_one(
    const float* __restrict__ s, __nv_bfloat16* __restrict__ h,
    __nv_bfloat16* __restrict__ l, unsigned n4)
{
    unsigned i = blockIdx.x * 256u + threadIdx.x;
    if (i >= n4) return;
    float4 v = ((const float4*)s)[i];
    float h0,h1,h2,h3,l0,l1,l2,l3;
    split1(v.x,h0,l0); split1(v.y,h1,l1); split1(v.z,h2,l2); split1(v.w,h3,l3);
    ((uint2*)h)[i] = make_uint2(pack2(h0,h1), pack2(h2,h3));
    ((uint2*)l)[i] = make_uint2(pack2(l0,l1), pack2(l2,l3));
}

// ---------------- weight transpose + split: Th[n][k] = hi(W[k][n]) ---------
struct WT5 { const float* w[5]; __nv_bfloat16* h[5]; __nv_bfloat16* l[5]; };

__global__ __launch_bounds__(256) void convert_wT(WT5 wt)
{
    __shared__ float tile[32][33];
    const float* W = wt.w[blockIdx.z];
    __nv_bfloat16* Th = wt.h[blockIdx.z];
    __nv_bfloat16* Tl = wt.l[blockIdx.z];
    int bx = blockIdx.x, by = blockIdx.y;
    int tx = threadIdx.x & 31, ty = threadIdx.x >> 5;
#pragma unroll
    for (int i = 0; i < 4; i++)
        tile[ty + i * 8][tx] = W[(size_t)(by * 32 + ty + i * 8) * DM + bx * 32 + tx];
    __syncthreads();
#pragma unroll
    for (int i = 0; i < 4; i++) {
        float x = tile[tx][ty + i * 8];
        float h, l;
        split1(x, h, l);
        size_t o = (size_t)(bx * 32 + ty + i * 8) * DM + by * 32 + tx;
        Th[o] = __float2bfloat16_rn(h);
        Tl[o] = __float2bfloat16_rn(l);
    }
}

// ================= mma.sync bf16 3-pass GEMM v3 ============================
// 512 thr, 16 warps (4x4), warp tile 32x32, CTA 128x128.
// A and B (pre-transposed weights) both staged via cp.async, 3-stage pipeline,
// fragments via ldmatrix.x4.
#define GSTRIDE 20
#define AWORDS  (128*GSTRIDE)
#define STAGEW  (4*AWORDS)             /* 40KB/stage */
#define NSTAGE  3
#define GSMEM_BYTES (NSTAGE*STAGEW*4)  /* 122880 */

static __device__ __forceinline__ void store_pair(
    float* C, int mode, int rowsPer, int r, int cn, float x, float y, int M)
{
    if (r >= M) return;
    float2 v = make_float2(x, y);
    if (mode == 0) {
        *(float2*)&C[(size_t)r * DM + cn] = v;
    } else {
        int b = r / rowsPer, rr = r - b * rowsPer;
        int h = cn >> 6, e = cn & 63;
        *(float2*)&C[((size_t)(b * H_ + h) * rowsPer + rr) * E_ + e] = v;
    }
}

__global__ __launch_bounds__(512, 1) void mma_gemm(
    const __nv_bfloat16* __restrict__ Ah, const __nv_bfloat16* __restrict__ Al,
    const __nv_bfloat16* __restrict__ Bth, const __nv_bfloat16* __restrict__ Btl,
    float* __restrict__ C, int M, int mode, int rowsPer)
{
    extern __shared__ uint32_t smw[];
    int tid = threadIdx.x, lane = tid & 31, wid = tid >> 5;
    int g = lane >> 2, t = lane & 3;
    int wm = wid & 3, wn = wid >> 2;
    int m0 = blockIdx.x * 128, n0 = blockIdx.y * 128;

    float acc[2][4][4];
#pragma unroll
    for (int i = 0; i < 2; i++)
#pragma unroll
        for (int j = 0; j < 4; j++)
#pragma unroll
            for (int q = 0; q < 4; q++) acc[i][j][q] = 0.f;

    // copier mapping: tid<256 -> A, else -> B(transposed weights)
    int cu = tid & 255;
    int crow = cu >> 1, chalf = cu & 1;
    bool isA = tid < 256;
    int crowA = (m0 + crow < M) ? crow : ((M - 1 - m0) > 0 ? (M - 1 - m0) : 0);
    const __nv_bfloat16* srcH = isA ? (Ah + (size_t)(m0 + crowA) * DM)
                                    : (Bth + (size_t)(n0 + crow) * DM);
    const __nv_bfloat16* srcL = isA ? (Al + (size_t)(m0 + crowA) * DM)
                                    : (Btl + (size_t)(n0 + crow) * DM);
    uint32_t smb = smem_u32(smw);
    uint32_t dstH = (isA ? 0u : 2u * AWORDS) + crow * GSTRIDE + chalf * 8;

    auto issue = [&](int ic, int stage) {
        const __nv_bfloat16* ph = srcH + ic * KCH + chalf * 16;
        const __nv_bfloat16* pl = srcL + ic * KCH + chalf * 16;
        uint32_t wh = stage * STAGEW + dstH;
        cpasync16(smb + wh * 4, ph);
        cpasync16(smb + (wh + 4) * 4, ph + 8);
        cpasync16(smb + (wh + AWORDS) * 4, pl);
        cpasync16(smb + (wh + AWORDS + 4) * 4, pl + 8);
    };

    // ldmatrix lane-address components (word units)
    int arow = wm * 32 + (lane & 7) + ((lane >> 3) & 1) * 8;  // + i*16
    int acol = (lane >> 4) * 4;                               // + ks*8
    int brow = wn * 32 + (lane & 7) + (lane >> 4) * 8;        // + p*16
    int bcol = ((lane >> 3) & 1) * 4;                         // + ks*8

    // prologue
    issue(0, 0); CP_COMMIT();
    issue(1, 1); CP_COMMIT();

    for (int ic = 0; ic < NCHUNK; ic++) {
        int buf = ic % NSTAGE;
        CP_WAIT1();
        __syncthreads();
        if (ic + 2 < NCHUNK) issue(ic + 2, (ic + 2) % NSTAGE);
        CP_COMMIT();

        uint32_t stage0 = smb + (buf * STAGEW) * 4;
#pragma unroll
        for (int ks = 0; ks < 2; ks++) {
            uint32_t ah[2][4], al[2][4], bh[2][4], bl[2][4];
#pragma unroll
            for (int i = 0; i < 2; i++) {
                uint32_t ao = stage0 + ((arow + i * 16) * GSTRIDE + acol + ks * 8) * 4;
                ldsm4(ah[i], ao);
                ldsm4(al[i], ao + AWORDS * 4);
            }
#pragma unroll
            for (int p = 0; p < 2; p++) {
                uint32_t bo = stage0 + (2 * AWORDS + (brow + p * 16) * GSTRIDE + bcol + ks * 8) * 4;
                ldsm4(bh[p], bo);
                ldsm4(bl[p], bo + AWORDS * 4);
            }
#pragma unroll
            for (int i = 0; i < 2; i++) {
#pragma unroll
                for (int p = 0; p < 2; p++) {
                    mma_bf16(acc[i][2*p],   ah[i], &bh[p][0]);
                    mma_bf16(acc[i][2*p+1], ah[i], &bh[p][2]);
                }
#pragma unroll
                for (int p = 0; p < 2; p++) {
                    mma_bf16(acc[i][2*p],   ah[i], &bl[p][0]);
                    mma_bf16(acc[i][2*p+1], ah[i], &bl[p][2]);
                }
#pragma unroll
                for (int p = 0; p < 2; p++) {
                    mma_bf16(acc[i][2*p],   al[i], &bh[p][0]);
                    mma_bf16(acc[i][2*p+1], al[i], &bh[p][2]);
                }
            }
        }
    }

#pragma unroll
    for (int i = 0; i < 2; i++) {
        int r = m0 + wm * 32 + i * 16 + g;
#pragma unroll
        for (int j = 0; j < 4; j++) {
            int cn = n0 + wn * 32 + j * 8 + t * 2;
            store_pair(C, mode, rowsPer, r,     cn, acc[i][j][0], acc[i][j][1], M);
            store_pair(C, mode, rowsPer, r + 8, cn, acc[i][j][2], acc[i][j][3], M);
        }
    }
}

// ---------------- scores v2 ----------------
__global__ __launch_bounds__(256) void scores_kernel()
{
    int bh = blockIdx.x, stile = blockIdx.y;
    int tid = threadIdx.x;
    int s = stile * 256 + tid;

    __shared__ float csS[G_ * 64];
    ((float4*)csS)[tid] = ((const float4*)(g_cs + (size_t)bh * G_ * 64))[tid];
    __syncthreads();

    float kkr[64];
    const float4* kp = (const float4*)(g_kk + ((size_t)bh * S_ + s) * 64);
#pragma unroll
    for (int i = 0; i < 16; i++) {
        float4 v = kp[i];
        kkr[i*4] = v.x; kkr[i*4+1] = v.y; kkr[i*4+2] = v.z; kkr[i*4+3] = v.w;
    }

    double local = 0.0;
#pragma unroll
    for (int g = 0; g < G_; g++) {
        float d = 0.f;
#pragma unroll
        for (int e = 0; e < 64; e++) d += csS[g * 64 + e] * kkr[e];
        d *= 0.125f;
        g_scores[((size_t)(bh * G_ + g)) * S_ + s] = d;
        local += (double)d;
    }

    __shared__ double sh[256];
    sh[tid] = local;
    __syncthreads();
    for (int o = 128; o; o >>= 1) {
        if (tid < o) sh[tid] += sh[tid + o];
        __syncthreads();
    }
    if (tid == 0) g_partial[stile * G_ + bh] = sh[0];
}

__global__ __launch_bounds__(128) void mean_kernel()
{
    __shared__ double sh[128];
    int t = threadIdx.x;
    sh[t] = g_partial[t];
    __syncthreads();
    for (int o = 64; o; o >>= 1) {
        if (t < o) sh[t] += sh[t + o];
        __syncthreads();
    }
    if (t == 0) g_mean = (float)(sh[0] / (double)((size_t)NCHAIN * S_));
}

__global__ __launch_bounds__(256) void wexp_kernel()
{
    int i = blockIdx.x * 256 + threadIdx.x;
    g_wexp[i] = expf(g_scores[i] - g_mean);
}

// ---------------- chunk sums v2 ----------------
__global__ __launch_bounds__(512) void chunk_sums_kernel()
{
    int bh = blockIdx.x, c = blockIdx.y;
    int tid = threadIdx.x;
    int g = tid >> 5, lane = tid & 31;

    __shared__ float kkS[CT * 64], vsS[CT * 64];
    ((float4*)kkS)[tid] = ((const float4*)(g_kk + ((size_t)bh * S_ + c * CT) * 64))[tid];
    ((float4*)vsS)[tid] = ((const float4*)(g_vs + ((size_t)bh * S_ + c * CT) * 64))[tid];

    int chain = bh * G_ + g;
    float wreg = g_wexp[(size_t)chain * S_ + c * CT + lane];
    __syncthreads();

    float nw = 0.f, ak0 = 0.f, ak1 = 0.f, av0 = 0.f, av1 = 0.f;
#pragma unroll
    for (int t = 0; t < CT; t++) {
        float w = __shfl_sync(0xffffffffu, wreg, t);
        nw += w;
        ak0 += w * kkS[t * 64 + lane];
        ak1 += w * kkS[t * 64 + lane + 32];
        av0 += w * vsS[t * 64 + lane];
        av1 += w * vsS[t * 64 + lane + 32];
    }
    float* op = g_chunk + ((size_t)chain * CH + c) * REC;
    op[1 + lane]  = ak0;
    op[33 + lane] = ak1;
    op[65 + lane] = av0;
    op[97 + lane] = av1;
    if (lane == 0) op[0] = nw;
}

__global__ __launch_bounds__(160) void chunk_prefix_kernel()
{
    int chain = blockIdx.x;
    int t = threadIdx.x;
    if (t >= 129) return;
    float run = 0.f;
    for (int c = 0; c < CH; c++) {
        size_t idx = ((size_t)chain * CH + c) * REC + t;
        float v = g_chunk[idx];
        g_chunk[idx] = run;
        run += v;
    }
}

// ---------------- fused scan ----------------
__global__ __launch_bounds__(512) void attn_scan_kernel()
{
    int bh = blockIdx.x, c = blockIdx.y;
    int tid = threadIdx.x;
    int g = tid >> 5, lane = tid & 31;

    __shared__ float kkS[CT * 64], vsS[CT * 64], qsS[CT * 64];
    __shared__ float wl[2][16];
    __shared__ float ybuf[2][16][64];

    const float* kkBase = g_kk + ((size_t)bh * S_ + c * CT) * E_;
    const float* vsBase = g_vs + ((size_t)bh * S_ + c * CT) * E_;
    const float* qsBase = g_qs + ((size_t)bh * S_ + c * CT) * E_;
    ((float4*)kkS)[tid] = ((const float4*)kkBase)[tid];
    ((float4*)vsS)[tid] = ((const float4*)vsBase)[tid];
    ((float4*)qsS)[tid] = ((const float4*)qsBase)[tid];

    const float* pf = g_chunk + ((size_t)(bh * G_ + g) * CH + c) * REC;
    float nw  = pf[0];
    float skA = pf[1 + lane];
    float skB = pf[1 + 32 + lane];
    float svA = pf[65 + lane];
    float svB = pf[65 + 32 + lane];
    float wchunk = g_wexp[(size_t)(bh * G_ + g) * S_ + c * CT + lane];

    int b = bh >> 3, h = bh & 7;
    float* outBase = g_attn + ((size_t)b * S_ + c * CT) * DM + h * E_;
    __syncthreads();

    for (int t = 0; t < CT; t++) {
        int p = t & 1;
        float w = __shfl_sync(0xffffffffu, wchunk, t);
        nw  += w;
        skA += w * kkS[t * 64 + lane];  skB += w * kkS[t * 64 + lane + 32];
        svA += w * vsS[t * 64 + lane];  svB += w * vsS[t * 64 + lane + 32];

        float d = qsS[t * 64 + lane] * skA + qsS[t * 64 + lane + 32] * skB;
#pragma unroll
        for (int o = 16; o; o >>= 1) d += __shfl_xor_sync(0xffffffffu, d, o);
        float nwc = fmaxf(nw, 1e-8f);
        if (lane == 0) wl[p][g] = d / nwc;
        __syncthreads();

        float x = (lane < 16) ? wl[p][lane] : -1e30f;
        float m = x;
#pragma unroll
        for (int o = 16; o; o >>= 1) m = fmaxf(m, __shfl_xor_sync(0xffffffffu, m, o));
        float e = (lane < 16) ? expf(x - m) : 0.f;
        float ss = e;
#pragma unroll
        for (int o = 16; o; o >>= 1) ss += __shfl_xor_sync(0xffffffffu, ss, o);
        float eg = __shfl_sync(0xffffffffu, e, g);
        float scale = (eg / ss) / nwc;

        ybuf[p][g][lane]      = scale * svA;
        ybuf[p][g][lane + 32] = scale * svB;
        __syncthreads();

        if (tid < 64) {
            float o = 0.f;
#pragma unroll
            for (int gg = 0; gg < 16; gg++) o += ybuf[p][gg][tid];
            outBase[(size_t)t * DM + tid] = o;
        }
    }
}

// ---------------- launch ---------------------------------------------------
extern "C" void kernel_launch(void* const* d_in, const int* in_sizes, int n_in,
                              void* d_out, int out_size)
{
    const float* q   = (const float*)d_in[0];
    const float* k   = (const float*)d_in[1];
    const float* v   = (const float*)d_in[2];
    const float* ctx = (const float*)d_in[3];

    typedef __nv_bfloat16 bf;
    static float *p_qs = nullptr, *p_kk, *p_vs, *p_cs, *p_attn;
    static bf *qh,*ql,*kh,*kl,*vh,*vl,*ch,*cl;
    static bf *wqh,*wql,*wkh,*wkl,*wvh,*wvl,*woh,*wol,*wch,*wcl;
    static bf *ah,*al;
    if (!p_qs) {
        cudaGetSymbolAddress((void**)&p_qs,   g_qs);
        cudaGetSymbolAddress((void**)&p_kk,   g_kk);
        cudaGetSymbolAddress((void**)&p_vs,   g_vs);
        cudaGetSymbolAddress((void**)&p_cs,   g_cs);
        cudaGetSymbolAddress((void**)&p_attn, g_attn);
        cudaGetSymbolAddress((void**)&qh, g_qh4);  cudaGetSymbolAddress((void**)&ql, g_ql4);
        cudaGetSymbolAddress((void**)&kh, g_kh4);  cudaGetSymbolAddress((void**)&kl, g_kl4);
        cudaGetSymbolAddress((void**)&vh, g_vh4);  cudaGetSymbolAddress((void**)&vl, g_vl4);
        cudaGetSymbolAddress((void**)&ch, g_ch4);  cudaGetSymbolAddress((void**)&cl, g_cl4);
        cudaGetSymbolAddress((void**)&wqh, g_wqh4); cudaGetSymbolAddress((void**)&wql, g_wql4);
        cudaGetSymbolAddress((void**)&wkh, g_wkh4); cudaGetSymbolAddress((void**)&wkl, g_wkl4);
        cudaGetSymbolAddress((void**)&wvh, g_wvh4); cudaGetSymbolAddress((void**)&wvl, g_wvl4);
        cudaGetSymbolAddress((void**)&woh, g_woh4); cudaGetSymbolAddress((void**)&wol, g_wol4);
        cudaGetSymbolAddress((void**)&wch, g_wch4); cudaGetSymbolAddress((void**)&wcl, g_wcl4);
        cudaGetSymbolAddress((void**)&ah, g_ah4);   cudaGetSymbolAddress((void**)&al, g_al4);
        cudaFuncSetAttribute(mma_gemm, cudaFuncAttributeMaxDynamicSharedMemorySize, GSMEM_BYTES);
    }

    const unsigned N_BIG = (B_*S_*DM)/4;
    const unsigned N_CTX = (B_*G_*DM)/4;

    Conv4 c4;
    c4.seg[0] = { q,   qh, ql, N_BIG };
    c4.seg[1] = { k,   kh, kl, N_BIG };
    c4.seg[2] = { v,   vh, vl, N_BIG };
    c4.seg[3] = { ctx, ch, cl, N_CTX };
    unsigned total4 = 3 * N_BIG + N_CTX;
    convert_act<<<(total4 + 255) / 256, 256>>>(c4, total4);

    WT5 wt;
    wt.w[0] = (const float*)d_in[4]; wt.h[0] = wqh; wt.l[0] = wql;
    wt.w[1] = (const float*)d_in[5]; wt.h[1] = wkh; wt.l[1] = wkl;
    wt.w[2] = (const float*)d_in[6]; wt.h[2] = wvh; wt.l[2] = wvl;
    wt.w[3] = (const float*)d_in[7]; wt.h[3] = woh; wt.l[3] = wol;
    wt.w[4] = (const float*)d_in[8]; wt.h[4] = wch; wt.l[4] = wcl;
    convert_wT<<<dim3(16, 16, 5), 256>>>(wt);

    mma_gemm<<<dim3(1, 4),  512, GSMEM_BYTES>>>(ch, cl, wch, wcl, p_cs, B_ * G_, 1, G_);
    mma_gemm<<<dim3(32, 4), 512, GSMEM_BYTES>>>(qh, ql, wqh, wql, p_qs, B_ * S_, 1, S_);
    mma_gemm<<<dim3(32, 4), 512, GSMEM_BYTES>>>(kh, kl, wkh, wkl, p_kk, B_ * S_, 1, S_);
    mma_gemm<<<dim3(32, 4), 512, GSMEM_BYTES>>>(vh, vl, wvh, wvl, p_vs, B_ * S_, 1, S_);

    scores_kernel<<<dim3(G_, 8), 256>>>();
    mean_kernel<<<1, 128>>>();
    wexp_kernel<<<(NCHAIN * S_) / 256, 256>>>();
    chunk_sums_kernel<<<dim3(G_, CH), 512>>>();
    chunk_prefix_kernel<<<NCHAIN, 160>>>();
    attn_scan_kernel<<<dim3(B_ * H_, CH), 512>>>();

    convert_one<<<N_BIG / 256, 256>>>(p_attn, ah, al, N_BIG);
    mma_gemm<<<dim3(32, 4), 512, GSMEM_BYTES>>>(ah, al, woh, wol, (float*)d_out, B_ * S_, 0, 0);
}

// round 11
// speedup vs baseline: 2.1730x; 1.1243x over previous
#include <cuda_runtime.h>
#include <cuda_bf16.h>
#include <cstdint>

#define B_   2
#define H_   8
#define G_   16
#define S_   2048
#define E_   64
#define DM   512
#define CT   32
#define CH   (S_/CT)
#define NCHAIN (B_*H_*G_)
#define REC  132
#define KCH  32
#define NCHUNK (DM/KCH)

// ---------------- fp32 scratch ----------------
__device__ float  g_qs[B_*H_*S_*E_];
__device__ float  g_kk[B_*H_*S_*E_];
__device__ float  g_vs[B_*H_*S_*E_];
__device__ float  g_cs[B_*H_*G_*E_];
__device__ float  g_scores[NCHAIN*S_];
__device__ float  g_wexp[NCHAIN*S_];
__device__ float  g_chunk[NCHAIN*CH*REC];
__device__ float  g_attn[B_*S_*DM];
__device__ double g_partial[256];
__device__ float  g_mean;

// ---------------- bf16 hi/lo buffers ----------------
__device__ uint4 g_qh4[262144], g_ql4[262144];
__device__ uint4 g_kh4[262144], g_kl4[262144];
__device__ uint4 g_vh4[262144], g_vl4[262144];
__device__ uint4 g_ch4[2048],   g_cl4[2048];
// transposed (n-major) weights
__device__ uint4 g_wqh4[32768], g_wql4[32768];
__device__ uint4 g_wkh4[32768], g_wkl4[32768];
__device__ uint4 g_wvh4[32768], g_wvl4[32768];
__device__ uint4 g_woh4[32768], g_wol4[32768];
__device__ uint4 g_wch4[32768], g_wcl4[32768];
__device__ uint4 g_ah4[262144], g_al4[262144];

// ---------------- helpers ----------------
static __device__ __forceinline__ uint32_t pack2(float a, float b) {
    __nv_bfloat162 t = __floats2bfloat162_rn(a, b);
    return *reinterpret_cast<uint32_t*>(&t);
}
static __device__ __forceinline__ void split1(float x, float& hi, float& lo) {
    __nv_bfloat16 h = __float2bfloat16_rn(x);
    hi = __bfloat162float(h);
    lo = x - hi;
}
static __device__ __forceinline__ void mma_bf16(float* c, const uint32_t* a, const uint32_t* b) {
    asm volatile(
        "mma.sync.aligned.m16n8k16.row.col.f32.bf16.bf16.f32 "
        "{%0,%1,%2,%3}, {%4,%5,%6,%7}, {%8,%9}, {%0,%1,%2,%3};"
        : "+f"(c[0]), "+f"(c[1]), "+f"(c[2]), "+f"(c[3])
        : "r"(a[0]), "r"(a[1]), "r"(a[2]), "r"(a[3]), "r"(b[0]), "r"(b[1]));
}
static __device__ __forceinline__ uint32_t smem_u32(const void* p) {
    uint32_t a;
    asm("{ .reg .u64 t; cvta.to.shared.u64 t, %1; cvt.u32.u64 %0, t; }" : "=r"(a) : "l"(p));
    return a;
}
static __device__ __forceinline__ void cpasync16(uint32_t dst, const void* src) {
    asm volatile("cp.async.cg.shared.global [%0], [%1], 16;" :: "r"(dst), "l"(src));
}
#define CP_COMMIT() asm volatile("cp.async.commit_group;" ::: "memory")
#define CP_WAIT1()  asm volatile("cp.async.wait_group 1;" ::: "memory")
static __device__ __forceinline__ void ldsm4(uint32_t* r, uint32_t addr) {
    asm volatile("ldmatrix.sync.aligned.m8n8.x4.shared.b16 {%0,%1,%2,%3}, [%4];"
        : "=r"(r[0]), "=r"(r[1]), "=r"(r[2]), "=r"(r[3]) : "r"(addr));
}

// ---------------- activation hi/lo split ----------------
struct ConvSeg { const float* s; __nv_bfloat16* h; __nv_bfloat16* l; unsigned n4; };
struct Conv4 { ConvSeg seg[4]; };

__global__ __launch_bounds__(256) void convert_act(Conv4 c, unsigned total4)
{
    unsigned i = blockIdx.x * 256u + threadIdx.x;
    if (i >= total4) return;
    unsigned off = i;
#pragma unroll
    for (int s = 0; s < 4; s++) {
        unsigned n4 = c.seg[s].n4;
        if (off < n4) {
            float4 v = ((const float4*)c.seg[s].s)[off];
            float h0,h1,h2,h3,l0,l1,l2,l3;
            split1(v.x,h0,l0); split1(v.y,h1,l1); split1(v.z,h2,l2); split1(v.w,h3,l3);
            ((uint2*)c.seg[s].h)[off] = make_uint2(pack2(h0,h1), pack2(h2,h3));
            ((uint2*)c.seg[s].l)[off] = make_uint2(pack2(l0,l1), pack2(l2,l3));
            return;
        }
        off -= n4;
    }
}

__global__ __launch_bounds__(256) void convert_one(
    const float* __restrict__ s, __nv_bfloat16* __restrict__ h,
    __nv_bfloat16* __restrict__ l, unsigned n4)
{
    unsigned i = blockIdx.x * 256u + threadIdx.x;
    if (i >= n4) return;
    float4 v = ((const float4*)s)[i];
    float h0,h1,h2,h3,l0,l1,l2,l3;
    split1(v.x,h0,l0); split1(v.y,h1,l1); split1(v.z,h2,l2); split1(v.w,h3,l3);
    ((uint2*)h)[i] = make_uint2(pack2(h0,h1), pack2(h2,h3));
    ((uint2*)l)[i] = make_uint2(pack2(l0,l1), pack2(l2,l3));
}

// ---------------- weight transpose + split ----------------
struct WT5 { const float* w[5]; __nv_bfloat16* h[5]; __nv_bfloat16* l[5]; };

__global__ __launch_bounds__(256) void convert_wT(WT5 wt)
{
    __shared__ float tile[32][33];
    const float* W = wt.w[blockIdx.z];
    __nv_bfloat16* Th = wt.h[blockIdx.z];
    __nv_bfloat16* Tl = wt.l[blockIdx.z];
    int bx = blockIdx.x, by = blockIdx.y;
    int tx = threadIdx.x & 31, ty = threadIdx.x >> 5;
#pragma unroll
    for (int i = 0; i < 4; i++)
        tile[ty + i * 8][tx] = W[(size_t)(by * 32 + ty + i * 8) * DM + bx * 32 + tx];
    __syncthreads();
#pragma unroll
    for (int i = 0; i < 4; i++) {
        float x = tile[tx][ty + i * 8];
        float h, l;
        split1(x, h, l);
        size_t o = (size_t)(bx * 32 + ty + i * 8) * DM + by * 32 + tx;
        Th[o] = __float2bfloat16_rn(h);
        Tl[o] = __float2bfloat16_rn(l);
    }
}

// ================= mma.sync bf16 3-pass GEMM v4 ============================
// 256 thr, 8 warps (2m x 4n), warp tile 32x32, CTA tile 64x128.
// 3-stage cp.async pipeline, ldmatrix fragments, 2 CTAs/SM.
#define GSTRIDE 20
#define AW      (64*GSTRIDE)     /* 1280 words */
#define BW      (128*GSTRIDE)    /* 2560 words */
#define STW     (2*AW + 2*BW)    /* 7680 words = 30KB/stage */
#define NSTAGE  3
#define GSMEM_BYTES (NSTAGE*STW*4)   /* 92160 */

struct GemmEnt {
    const __nv_bfloat16 *Ah, *Al, *Bth, *Btl;
    float* C;
    int M, rowsPer, mode;
};
struct Gemm4 { GemmEnt e[4]; };

static __device__ __forceinline__ void store_pair(
    float* C, int mode, int rowsPer, int r, int cn, float x, float y, int M)
{
    if (r >= M) return;
    float2 v = make_float2(x, y);
    if (mode == 0) {
        *(float2*)&C[(size_t)r * DM + cn] = v;
    } else {
        int b = r / rowsPer, rr = r - b * rowsPer;
        int h = cn >> 6, e = cn & 63;
        *(float2*)&C[((size_t)(b * H_ + h) * rowsPer + rr) * E_ + e] = v;
    }
}

static __device__ __forceinline__ void gemm_body(
    const GemmEnt Q, int m0, int n0)
{
    extern __shared__ uint32_t smw[];
    int tid = threadIdx.x, lane = tid & 31, wid = tid >> 5;
    int g = lane >> 2, t = lane & 3;
    int wm = wid & 1, wn = wid >> 1;

    float acc[2][4][4];
#pragma unroll
    for (int i = 0; i < 2; i++)
#pragma unroll
        for (int j = 0; j < 4; j++)
#pragma unroll
            for (int q = 0; q < 4; q++) acc[i][j][q] = 0.f;

    // copier segments: A threads (tid<128) one row-half; B threads two
    bool isA = tid < 128;
    int u = isA ? tid : (tid - 128);
    const __nv_bfloat16* segH[2];
    const __nv_bfloat16* segL[2];
    uint32_t segD[2];
    uint32_t loOff;
    int nseg;
    if (isA) {
        int row = u >> 1, half = u & 1;
        int rowC = row;
        if (m0 + rowC >= Q.M) { rowC = Q.M - 1 - m0; if (rowC < 0) rowC = 0; }
        segH[0] = Q.Ah + (size_t)(m0 + rowC) * DM + half * 16;
        segL[0] = Q.Al + (size_t)(m0 + rowC) * DM + half * 16;
        segD[0] = row * GSTRIDE + half * 8;
        loOff = AW; nseg = 1;
        segH[1] = segH[0]; segL[1] = segL[0]; segD[1] = segD[0];
    } else {
        loOff = BW; nseg = 2;
#pragma unroll
        for (int s = 0; s < 2; s++) {
            int unit = u + s * 128;
            int row = unit >> 1, half = unit & 1;
            segH[s] = Q.Bth + (size_t)(n0 + row) * DM + half * 16;
            segL[s] = Q.Btl + (size_t)(n0 + row) * DM + half * 16;
            segD[s] = 2 * AW + row * GSTRIDE + half * 8;
        }
    }
    uint32_t smb = smem_u32(smw);

    auto issue = [&](int ic, int stage) {
#pragma unroll
        for (int s = 0; s < 2; s++) {
            if (s >= nseg) break;
            const __nv_bfloat16* ph = segH[s] + ic * KCH;
            const __nv_bfloat16* pl = segL[s] + ic * KCH;
            uint32_t w = stage * STW + segD[s];
            cpasync16(smb + w * 4, ph);
            cpasync16(smb + (w + 4) * 4, ph + 8);
            cpasync16(smb + (w + loOff) * 4, pl);
            cpasync16(smb + (w + loOff + 4) * 4, pl + 8);
        }
    };

    // ldmatrix lane addresses (word units)
    int arow = wm * 32 + (lane & 7) + ((lane >> 3) & 1) * 8;
    int acol = (lane >> 4) * 4;
    int brow = wn * 32 + (lane & 7) + (lane >> 4) * 8;
    int bcol = ((lane >> 3) & 1) * 4;

    issue(0, 0); CP_COMMIT();
    issue(1, 1); CP_COMMIT();

    for (int ic = 0; ic < NCHUNK; ic++) {
        int buf = ic % NSTAGE;
        CP_WAIT1();
        __syncthreads();
        if (ic + 2 < NCHUNK) issue(ic + 2, (ic + 2) % NSTAGE);
        CP_COMMIT();

        uint32_t stage0 = smb + (buf * STW) * 4;
#pragma unroll
        for (int ks = 0; ks < 2; ks++) {
            uint32_t ah[2][4], al[2][4], bh[2][4], bl[2][4];
#pragma unroll
            for (int i = 0; i < 2; i++) {
                uint32_t ao = stage0 + ((arow + i * 16) * GSTRIDE + acol + ks * 8) * 4;
                ldsm4(ah[i], ao);
                ldsm4(al[i], ao + AW * 4);
            }
#pragma unroll
            for (int p = 0; p < 2; p++) {
                uint32_t bo = stage0 + (2 * AW + (brow + p * 16) * GSTRIDE + bcol + ks * 8) * 4;
                ldsm4(bh[p], bo);
                ldsm4(bl[p], bo + BW * 4);
            }
#pragma unroll
            for (int i = 0; i < 2; i++) {
#pragma unroll
                for (int p = 0; p < 2; p++) {
                    mma_bf16(acc[i][2*p],   ah[i], &bh[p][0]);
                    mma_bf16(acc[i][2*p+1], ah[i], &bh[p][2]);
                }
#pragma unroll
                for (int p = 0; p < 2; p++) {
                    mma_bf16(acc[i][2*p],   ah[i], &bl[p][0]);
                    mma_bf16(acc[i][2*p+1], ah[i], &bl[p][2]);
                }
#pragma unroll
                for (int p = 0; p < 2; p++) {
                    mma_bf16(acc[i][2*p],   al[i], &bh[p][0]);
                    mma_bf16(acc[i][2*p+1], al[i], &bh[p][2]);
                }
            }
        }
    }

#pragma unroll
    for (int i = 0; i < 2; i++) {
        int r = m0 + wm * 32 + i * 16 + g;
#pragma unroll
        for (int j = 0; j < 4; j++) {
            int cn = n0 + wn * 32 + j * 8 + t * 2;
            store_pair(Q.C, Q.mode, Q.rowsPer, r,     cn, acc[i][j][0], acc[i][j][1], Q.M);
            store_pair(Q.C, Q.mode, Q.rowsPer, r + 8, cn, acc[i][j][2], acc[i][j][3], Q.M);
        }
    }
}

// merged ctx+q+k+v launch: bx 0 -> ctx, 1..64 -> q, 65..128 -> k, 129..192 -> v
__global__ __launch_bounds__(256, 2) void mma_gemm_multi(Gemm4 P)
{
    int bx = blockIdx.x;
    int z, xm;
    if (bx == 0) { z = 0; xm = 0; }
    else { z = 1 + ((bx - 1) >> 6); xm = (bx - 1) & 63; }
    gemm_body(P.e[z], xm * 64, blockIdx.y * 128);
}

__global__ __launch_bounds__(256, 2) void mma_gemm_one(GemmEnt Q)
{
    gemm_body(Q, blockIdx.x * 64, blockIdx.y * 128);
}

// ---------------- scores ----------------
__global__ __launch_bounds__(256) void scores_kernel()
{
    int bh = blockIdx.x, stile = blockIdx.y;
    int tid = threadIdx.x;
    int s = stile * 256 + tid;

    __shared__ float csS[G_ * 64];
    ((float4*)csS)[tid] = ((const float4*)(g_cs + (size_t)bh * G_ * 64))[tid];
    __syncthreads();

    float kkr[64];
    const float4* kp = (const float4*)(g_kk + ((size_t)bh * S_ + s) * 64);
#pragma unroll
    for (int i = 0; i < 16; i++) {
        float4 v = kp[i];
        kkr[i*4] = v.x; kkr[i*4+1] = v.y; kkr[i*4+2] = v.z; kkr[i*4+3] = v.w;
    }

    double local = 0.0;
#pragma unroll
    for (int g = 0; g < G_; g++) {
        float d = 0.f;
#pragma unroll
        for (int e = 0; e < 64; e++) d += csS[g * 64 + e] * kkr[e];
        d *= 0.125f;
        g_scores[((size_t)(bh * G_ + g)) * S_ + s] = d;
        local += (double)d;
    }

    __shared__ double sh[256];
    sh[tid] = local;
    __syncthreads();
    for (int o = 128; o; o >>= 1) {
        if (tid < o) sh[tid] += sh[tid + o];
        __syncthreads();
    }
    if (tid == 0) g_partial[stile * G_ + bh] = sh[0];
}

__global__ __launch_bounds__(128) void mean_kernel()
{
    __shared__ double sh[128];
    int t = threadIdx.x;
    sh[t] = g_partial[t];
    __syncthreads();
    for (int o = 64; o; o >>= 1) {
        if (t < o) sh[t] += sh[t + o];
        __syncthreads();
    }
    if (t == 0) g_mean = (float)(sh[0] / (double)((size_t)NCHAIN * S_));
}

__global__ __launch_bounds__(256) void wexp_kernel()
{
    int i = blockIdx.x * 256 + threadIdx.x;
    g_wexp[i] = expf(g_scores[i] - g_mean);
}

// ---------------- chunk sums ----------------
__global__ __launch_bounds__(512) void chunk_sums_kernel()
{
    int bh = blockIdx.x, c = blockIdx.y;
    int tid = threadIdx.x;
    int g = tid >> 5, lane = tid & 31;

    __shared__ float kkS[CT * 64], vsS[CT * 64];
    ((float4*)kkS)[tid] = ((const float4*)(g_kk + ((size_t)bh * S_ + c * CT) * 64))[tid];
    ((float4*)vsS)[tid] = ((const float4*)(g_vs + ((size_t)bh * S_ + c * CT) * 64))[tid];

    int chain = bh * G_ + g;
    float wreg = g_wexp[(size_t)chain * S_ + c * CT + lane];
    __syncthreads();

    float nw = 0.f, ak0 = 0.f, ak1 = 0.f, av0 = 0.f, av1 = 0.f;
#pragma unroll
    for (int t = 0; t < CT; t++) {
        float w = __shfl_sync(0xffffffffu, wreg, t);
        nw += w;
        ak0 += w * kkS[t * 64 + lane];
        ak1 += w * kkS[t * 64 + lane + 32];
        av0 += w * vsS[t * 64 + lane];
        av1 += w * vsS[t * 64 + lane + 32];
    }
    float* op = g_chunk + ((size_t)chain * CH + c) * REC;
    op[1 + lane]  = ak0;
    op[33 + lane] = ak1;
    op[65 + lane] = av0;
    op[97 + lane] = av1;
    if (lane == 0) op[0] = nw;
}

__global__ __launch_bounds__(160) void chunk_prefix_kernel()
{
    int chain = blockIdx.x;
    int t = threadIdx.x;
    if (t >= 129) return;
    float run = 0.f;
    for (int c = 0; c < CH; c++) {
        size_t idx = ((size_t)chain * CH + c) * REC + t;
        float v = g_chunk[idx];
        g_chunk[idx] = run;
        run += v;
    }
}

// ---------------- fused scan ----------------
__global__ __launch_bounds__(512) void attn_scan_kernel()
{
    int bh = blockIdx.x, c = blockIdx.y;
    int tid = threadIdx.x;
    int g = tid >> 5, lane = tid & 31;

    __shared__ float kkS[CT * 64], vsS[CT * 64], qsS[CT * 64];
    __shared__ float wl[2][16];
    __shared__ float ybuf[2][16][64];

    const float* kkBase = g_kk + ((size_t)bh * S_ + c * CT) * E_;
    const float* vsBase = g_vs + ((size_t)bh * S_ + c * CT) * E_;
    const float* qsBase = g_qs + ((size_t)bh * S_ + c * CT) * E_;
    ((float4*)kkS)[tid] = ((const float4*)kkBase)[tid];
    ((float4*)vsS)[tid] = ((const float4*)vsBase)[tid];
    ((float4*)qsS)[tid] = ((const float4*)qsBase)[tid];

    const float* pf = g_chunk + ((size_t)(bh * G_ + g) * CH + c) * REC;
    float nw  = pf[0];
    float skA = pf[1 + lane];
    float skB = pf[1 + 32 + lane];
    float svA = pf[65 + lane];
    float svB = pf[65 + 32 + lane];
    float wchunk = g_wexp[(size_t)(bh * G_ + g) * S_ + c * CT + lane];

    int b = bh >> 3, h = bh & 7;
    float* outBase = g_attn + ((size_t)b * S_ + c * CT) * DM + h * E_;
    __syncthreads();

    for (int t = 0; t < CT; t++) {
        int p = t & 1;
        float w = __shfl_sync(0xffffffffu, wchunk, t);
        nw  += w;
        skA += w * kkS[t * 64 + lane];  skB += w * kkS[t * 64 + lane + 32];
        svA += w * vsS[t * 64 + lane];  svB += w * vsS[t * 64 + lane + 32];

        float d = qsS[t * 64 + lane] * skA + qsS[t * 64 + lane + 32] * skB;
#pragma unroll
        for (int o = 16; o; o >>= 1) d += __shfl_xor_sync(0xffffffffu, d, o);
        float nwc = fmaxf(nw, 1e-8f);
        if (lane == 0) wl[p][g] = d / nwc;
        __syncthreads();

        float x = (lane < 16) ? wl[p][lane] : -1e30f;
        float m = x;
#pragma unroll
        for (int o = 16; o; o >>= 1) m = fmaxf(m, __shfl_xor_sync(0xffffffffu, m, o));
        float e = (lane < 16) ? expf(x - m) : 0.f;
        float ss = e;
#pragma unroll
        for (int o = 16; o; o >>= 1) ss += __shfl_xor_sync(0xffffffffu, ss, o);
        float eg = __shfl_sync(0xffffffffu, e, g);
        float scale = (eg / ss) / nwc;

        ybuf[p][g][lane]      = scale * svA;
        ybuf[p][g][lane + 32] = scale * svB;
        __syncthreads();

        if (tid < 64) {
            float o = 0.f;
#pragma unroll
            for (int gg = 0; gg < 16; gg++) o += ybuf[p][gg][tid];
            outBase[(size_t)t * DM + tid] = o;
        }
    }
}

// ---------------- launch ---------------------------------------------------
extern "C" void kernel_launch(void* const* d_in, const int* in_sizes, int n_in,
                              void* d_out, int out_size)
{
    const float* q   = (const float*)d_in[0];
    const float* k   = (const float*)d_in[1];
    const float* v   = (const float*)d_in[2];
    const float* ctx = (const float*)d_in[3];

    typedef __nv_bfloat16 bf;
    static float *p_qs = nullptr, *p_kk, *p_vs, *p_cs, *p_attn;
    static bf *qh,*ql,*kh,*kl,*vh,*vl,*ch,*cl;
    static bf *wqh,*wql,*wkh,*wkl,*wvh,*wvl,*woh,*wol,*wch,*wcl;
    static bf *ah,*al;
    if (!p_qs) {
        cudaGetSymbolAddress((void**)&p_qs,   g_qs);
        cudaGetSymbolAddress((void**)&p_kk,   g_kk);
        cudaGetSymbolAddress((void**)&p_vs,   g_vs);
        cudaGetSymbolAddress((void**)&p_cs,   g_cs);
        cudaGetSymbolAddress((void**)&p_attn, g_attn);
        cudaGetSymbolAddress((void**)&qh, g_qh4);  cudaGetSymbolAddress((void**)&ql, g_ql4);
        cudaGetSymbolAddress((void**)&kh, g_kh4);  cudaGetSymbolAddress((void**)&kl, g_kl4);
        cudaGetSymbolAddress((void**)&vh, g_vh4);  cudaGetSymbolAddress((void**)&vl, g_vl4);
        cudaGetSymbolAddress((void**)&ch, g_ch4);  cudaGetSymbolAddress((void**)&cl, g_cl4);
        cudaGetSymbolAddress((void**)&wqh, g_wqh4); cudaGetSymbolAddress((void**)&wql, g_wql4);
        cudaGetSymbolAddress((void**)&wkh, g_wkh4); cudaGetSymbolAddress((void**)&wkl, g_wkl4);
        cudaGetSymbolAddress((void**)&wvh, g_wvh4); cudaGetSymbolAddress((void**)&wvl, g_wvl4);
        cudaGetSymbolAddress((void**)&woh, g_woh4); cudaGetSymbolAddress((void**)&wol, g_wol4);
        cudaGetSymbolAddress((void**)&wch, g_wch4); cudaGetSymbolAddress((void**)&wcl, g_wcl4);
        cudaGetSymbolAddress((void**)&ah, g_ah4);   cudaGetSymbolAddress((void**)&al, g_al4);
        cudaFuncSetAttribute(mma_gemm_multi, cudaFuncAttributeMaxDynamicSharedMemorySize, GSMEM_BYTES);
        cudaFuncSetAttribute(mma_gemm_one,   cudaFuncAttributeMaxDynamicSharedMemorySize, GSMEM_BYTES);
    }

    const unsigned N_BIG = (B_*S_*DM)/4;
    const unsigned N_CTX = (B_*G_*DM)/4;

    Conv4 c4;
    c4.seg[0] = { q,   qh, ql, N_BIG };
    c4.seg[1] = { k,   kh, kl, N_BIG };
    c4.seg[2] = { v,   vh, vl, N_BIG };
    c4.seg[3] = { ctx, ch, cl, N_CTX };
    unsigned total4 = 3 * N_BIG + N_CTX;
    convert_act<<<(total4 + 255) / 256, 256>>>(c4, total4);

    WT5 wt;
    wt.w[0] = (const float*)d_in[4]; wt.h[0] = wqh; wt.l[0] = wql;
    wt.w[1] = (const float*)d_in[5]; wt.h[1] = wkh; wt.l[1] = wkl;
    wt.w[2] = (const float*)d_in[6]; wt.h[2] = wvh; wt.l[2] = wvl;
    wt.w[3] = (const float*)d_in[7]; wt.h[3] = woh; wt.l[3] = wol;
    wt.w[4] = (const float*)d_in[8]; wt.h[4] = wch; wt.l[4] = wcl;
    convert_wT<<<dim3(16, 16, 5), 256>>>(wt);

    Gemm4 P;
    P.e[0] = { ch, cl, wch, wcl, p_cs, B_ * G_, G_, 1 };
    P.e[1] = { qh, ql, wqh, wql, p_qs, B_ * S_, S_, 1 };
    P.e[2] = { kh, kl, wkh, wkl, p_kk, B_ * S_, S_, 1 };
    P.e[3] = { vh, vl, wvh, wvl, p_vs, B_ * S_, S_, 1 };
    mma_gemm_multi<<<dim3(193, 4), 256, GSMEM_BYTES>>>(P);

    scores_kernel<<<dim3(G_, 8), 256>>>();
    mean_kernel<<<1, 128>>>();
    wexp_kernel<<<(NCHAIN * S_) / 256, 256>>>();
    chunk_sums_kernel<<<dim3(G_, CH), 512>>>();
    chunk_prefix_kernel<<<NCHAIN, 160>>>();
    attn_scan_kernel<<<dim3(B_ * H_, CH), 512>>>();

    convert_one<<<N_BIG / 256, 256>>>(p_attn, ah, al, N_BIG);
    GemmEnt Qo = { ah, al, woh, wol, (float*)d_out, B_ * S_, S_, 0 };
    mma_gemm_one<<<dim3(64, 4), 256, GSMEM_BYTES>>>(Qo);
}

// round 12
// speedup vs baseline: 2.6065x; 1.1995x over previous
#include <cuda_runtime.h>
#include <cuda_bf16.h>
#include <cstdint>

#define B_   2
#define H_   8
#define G_   16
#define S_   2048
#define E_   64
#define DM   512
#define CT   32
#define CH   (S_/CT)
#define NCHAIN (B_*H_*G_)
#define REC  132
#define KCH  32
#define NCHUNK (DM/KCH)

// ---------------- fp32 scratch ----------------
__device__ float  g_qs[B_*H_*S_*E_];
__device__ float  g_kk[B_*H_*S_*E_];
__device__ float  g_vs[B_*H_*S_*E_];
__device__ float  g_cs[B_*H_*G_*E_];
__device__ float  g_scores[NCHAIN*S_];
__device__ float  g_wexp[NCHAIN*S_];
__device__ float  g_chunk[NCHAIN*CH*REC];
__device__ double g_partial[256];
__device__ float  g_mean;

// ---------------- bf16 hi/lo buffers ----------------
__device__ uint4 g_qh4[262144], g_ql4[262144];
__device__ uint4 g_kh4[262144], g_kl4[262144];
__device__ uint4 g_vh4[262144], g_vl4[262144];
__device__ uint4 g_ch4[2048],   g_cl4[2048];
__device__ uint4 g_wqh4[32768], g_wql4[32768];
__device__ uint4 g_wkh4[32768], g_wkl4[32768];
__device__ uint4 g_wvh4[32768], g_wvl4[32768];
__device__ uint4 g_woh4[32768], g_wol4[32768];
__device__ uint4 g_wch4[32768], g_wcl4[32768];
__device__ uint4 g_ah4[262144], g_al4[262144];

// ---------------- helpers ----------------
static __device__ __forceinline__ uint32_t pack2(float a, float b) {
    __nv_bfloat162 t = __floats2bfloat162_rn(a, b);
    return *reinterpret_cast<uint32_t*>(&t);
}
static __device__ __forceinline__ void split1(float x, float& hi, float& lo) {
    __nv_bfloat16 h = __float2bfloat16_rn(x);
    hi = __bfloat162float(h);
    lo = x - hi;
}
static __device__ __forceinline__ void mma_bf16(float* c, const uint32_t* a, const uint32_t* b) {
    asm volatile(
        "mma.sync.aligned.m16n8k16.row.col.f32.bf16.bf16.f32 "
        "{%0,%1,%2,%3}, {%4,%5,%6,%7}, {%8,%9}, {%0,%1,%2,%3};"
        : "+f"(c[0]), "+f"(c[1]), "+f"(c[2]), "+f"(c[3])
        : "r"(a[0]), "r"(a[1]), "r"(a[2]), "r"(a[3]), "r"(b[0]), "r"(b[1]));
}
static __device__ __forceinline__ uint32_t smem_u32(const void* p) {
    uint32_t a;
    asm("{ .reg .u64 t; cvta.to.shared.u64 t, %1; cvt.u32.u64 %0, t; }" : "=r"(a) : "l"(p));
    return a;
}
static __device__ __forceinline__ void cpasync16(uint32_t dst, const void* src) {
    asm volatile("cp.async.cg.shared.global [%0], [%1], 16;" :: "r"(dst), "l"(src));
}
#define CP_COMMIT() asm volatile("cp.async.commit_group;" ::: "memory")
#define CP_WAIT1()  asm volatile("cp.async.wait_group 1;" ::: "memory")
static __device__ __forceinline__ void ldsm4(uint32_t* r, uint32_t addr) {
    asm volatile("ldmatrix.sync.aligned.m8n8.x4.shared.b16 {%0,%1,%2,%3}, [%4];"
        : "=r"(r[0]), "=r"(r[1]), "=r"(r[2]), "=r"(r[3]) : "r"(addr));
}

// ---------------- activation hi/lo split ----------------
struct ConvSeg { const float* s; __nv_bfloat16* h; __nv_bfloat16* l; unsigned n4; };
struct Conv4 { ConvSeg seg[4]; };

__global__ __launch_bounds__(256) void convert_act(Conv4 c, unsigned total4)
{
    unsigned i = blockIdx.x * 256u + threadIdx.x;
    if (i >= total4) return;
    unsigned off = i;
#pragma unroll
    for (int s = 0; s < 4; s++) {
        unsigned n4 = c.seg[s].n4;
        if (off < n4) {
            float4 v = ((const float4*)c.seg[s].s)[off];
            float h0,h1,h2,h3,l0,l1,l2,l3;
            split1(v.x,h0,l0); split1(v.y,h1,l1); split1(v.z,h2,l2); split1(v.w,h3,l3);
            ((uint2*)c.seg[s].h)[off] = make_uint2(pack2(h0,h1), pack2(h2,h3));
            ((uint2*)c.seg[s].l)[off] = make_uint2(pack2(l0,l1), pack2(l2,l3));
            return;
        }
        off -= n4;
    }
}

// ---------------- weight transpose + split ----------------
struct WT5 { const float* w[5]; __nv_bfloat16* h[5]; __nv_bfloat16* l[5]; };

__global__ __launch_bounds__(256) void convert_wT(WT5 wt)
{
    __shared__ float tile[32][33];
    const float* W = wt.w[blockIdx.z];
    __nv_bfloat16* Th = wt.h[blockIdx.z];
    __nv_bfloat16* Tl = wt.l[blockIdx.z];
    int bx = blockIdx.x, by = blockIdx.y;
    int tx = threadIdx.x & 31, ty = threadIdx.x >> 5;
#pragma unroll
    for (int i = 0; i < 4; i++)
        tile[ty + i * 8][tx] = W[(size_t)(by * 32 + ty + i * 8) * DM + bx * 32 + tx];
    __syncthreads();
#pragma unroll
    for (int i = 0; i < 4; i++) {
        float x = tile[tx][ty + i * 8];
        float h, l;
        split1(x, h, l);
        size_t o = (size_t)(bx * 32 + ty + i * 8) * DM + by * 32 + tx;
        Th[o] = __float2bfloat16_rn(h);
        Tl[o] = __float2bfloat16_rn(l);
    }
}

// ================= mma.sync bf16 3-pass GEMM ===============================
#define GSTRIDE 20
#define AW      (64*GSTRIDE)
#define BW      (128*GSTRIDE)
#define STW     (2*AW + 2*BW)
#define NSTAGE  3
#define GSMEM_BYTES (NSTAGE*STW*4)

struct GemmEnt {
    const __nv_bfloat16 *Ah, *Al, *Bth, *Btl;
    float* C;
    int M, rowsPer, mode;
};
struct Gemm4 { GemmEnt e[4]; };

static __device__ __forceinline__ void store_pair(
    float* C, int mode, int rowsPer, int r, int cn, float x, float y, int M)
{
    if (r >= M) return;
    float2 v = make_float2(x, y);
    if (mode == 0) {
        *(float2*)&C[(size_t)r * DM + cn] = v;
    } else {
        int b = r / rowsPer, rr = r - b * rowsPer;
        int h = cn >> 6, e = cn & 63;
        *(float2*)&C[((size_t)(b * H_ + h) * rowsPer + rr) * E_ + e] = v;
    }
}

static __device__ __forceinline__ void gemm_body(
    const GemmEnt Q, int m0, int n0)
{
    extern __shared__ uint32_t smw[];
    int tid = threadIdx.x, lane = tid & 31, wid = tid >> 5;
    int g = lane >> 2, t = lane & 3;
    int wm = wid & 1, wn = wid >> 1;

    float acc[2][4][4];
#pragma unroll
    for (int i = 0; i < 2; i++)
#pragma unroll
        for (int j = 0; j < 4; j++)
#pragma unroll
            for (int q = 0; q < 4; q++) acc[i][j][q] = 0.f;

    bool isA = tid < 128;
    int u = isA ? tid : (tid - 128);
    const __nv_bfloat16* segH[2];
    const __nv_bfloat16* segL[2];
    uint32_t segD[2];
    uint32_t loOff;
    int nseg;
    if (isA) {
        int row = u >> 1, half = u & 1;
        int rowC = row;
        if (m0 + rowC >= Q.M) { rowC = Q.M - 1 - m0; if (rowC < 0) rowC = 0; }
        segH[0] = Q.Ah + (size_t)(m0 + rowC) * DM + half * 16;
        segL[0] = Q.Al + (size_t)(m0 + rowC) * DM + half * 16;
        segD[0] = row * GSTRIDE + half * 8;
        loOff = AW; nseg = 1;
        segH[1] = segH[0]; segL[1] = segL[0]; segD[1] = segD[0];
    } else {
        loOff = BW; nseg = 2;
#pragma unroll
        for (int s = 0; s < 2; s++) {
            int unit = u + s * 128;
            int row = unit >> 1, half = unit & 1;
            segH[s] = Q.Bth + (size_t)(n0 + row) * DM + half * 16;
            segL[s] = Q.Btl + (size_t)(n0 + row) * DM + half * 16;
            segD[s] = 2 * AW + row * GSTRIDE + half * 8;
        }
    }
    uint32_t smb = smem_u32(smw);

    auto issue = [&](int ic, int stage) {
#pragma unroll
        for (int s = 0; s < 2; s++) {
            if (s >= nseg) break;
            const __nv_bfloat16* ph = segH[s] + ic * KCH;
            const __nv_bfloat16* pl = segL[s] + ic * KCH;
            uint32_t w = stage * STW + segD[s];
            cpasync16(smb + w * 4, ph);
            cpasync16(smb + (w + 4) * 4, ph + 8);
            cpasync16(smb + (w + loOff) * 4, pl);
            cpasync16(smb + (w + loOff + 4) * 4, pl + 8);
        }
    };

    int arow = wm * 32 + (lane & 7) + ((lane >> 3) & 1) * 8;
    int acol = (lane >> 4) * 4;
    int brow = wn * 32 + (lane & 7) + (lane >> 4) * 8;
    int bcol = ((lane >> 3) & 1) * 4;

    issue(0, 0); CP_COMMIT();
    issue(1, 1); CP_COMMIT();

    for (int ic = 0; ic < NCHUNK; ic++) {
        int buf = ic % NSTAGE;
        CP_WAIT1();
        __syncthreads();
        if (ic + 2 < NCHUNK) issue(ic + 2, (ic + 2) % NSTAGE);
        CP_COMMIT();

        uint32_t stage0 = smb + (buf * STW) * 4;
#pragma unroll
        for (int ks = 0; ks < 2; ks++) {
            uint32_t ah[2][4], al[2][4], bh[2][4], bl[2][4];
#pragma unroll
            for (int i = 0; i < 2; i++) {
                uint32_t ao = stage0 + ((arow + i * 16) * GSTRIDE + acol + ks * 8) * 4;
                ldsm4(ah[i], ao);
                ldsm4(al[i], ao + AW * 4);
            }
#pragma unroll
            for (int p = 0; p < 2; p++) {
                uint32_t bo = stage0 + (2 * AW + (brow + p * 16) * GSTRIDE + bcol + ks * 8) * 4;
                ldsm4(bh[p], bo);
                ldsm4(bl[p], bo + BW * 4);
            }
#pragma unroll
            for (int i = 0; i < 2; i++) {
#pragma unroll
                for (int p = 0; p < 2; p++) {
                    mma_bf16(acc[i][2*p],   ah[i], &bh[p][0]);
                    mma_bf16(acc[i][2*p+1], ah[i], &bh[p][2]);
                }
#pragma unroll
                for (int p = 0; p < 2; p++) {
                    mma_bf16(acc[i][2*p],   ah[i], &bl[p][0]);
                    mma_bf16(acc[i][2*p+1], ah[i], &bl[p][2]);
                }
#pragma unroll
                for (int p = 0; p < 2; p++) {
                    mma_bf16(acc[i][2*p],   al[i], &bh[p][0]);
                    mma_bf16(acc[i][2*p+1], al[i], &bh[p][2]);
                }
            }
        }
    }

#pragma unroll
    for (int i = 0; i < 2; i++) {
        int r = m0 + wm * 32 + i * 16 + g;
#pragma unroll
        for (int j = 0; j < 4; j++) {
            int cn = n0 + wn * 32 + j * 8 + t * 2;
            store_pair(Q.C, Q.mode, Q.rowsPer, r,     cn, acc[i][j][0], acc[i][j][1], Q.M);
            store_pair(Q.C, Q.mode, Q.rowsPer, r + 8, cn, acc[i][j][2], acc[i][j][3], Q.M);
        }
    }
}

__global__ __launch_bounds__(256, 2) void mma_gemm_multi(Gemm4 P)
{
    int bx = blockIdx.x;
    int z, xm;
    if (bx == 0) { z = 0; xm = 0; }
    else { z = 1 + ((bx - 1) >> 6); xm = (bx - 1) & 63; }
    gemm_body(P.e[z], xm * 64, blockIdx.y * 128);
}

__global__ __launch_bounds__(256, 2) void mma_gemm_one(GemmEnt Q)
{
    gemm_body(Q, blockIdx.x * 64, blockIdx.y * 128);
}

// ---------------- scores: grid (16 bh, 16 stile), 128 thr -------------------
__global__ __launch_bounds__(128) void scores_kernel()
{
    int bh = blockIdx.x, stile = blockIdx.y;
    int tid = threadIdx.x;
    int s = stile * 128 + tid;

    __shared__ float csS[G_ * 64];
    ((float4*)csS)[tid]       = ((const float4*)(g_cs + (size_t)bh * G_ * 64))[tid];
    ((float4*)csS)[tid + 128] = ((const float4*)(g_cs + (size_t)bh * G_ * 64))[tid + 128];
    __syncthreads();

    float kkr[64];
    const float4* kp = (const float4*)(g_kk + ((size_t)bh * S_ + s) * 64);
#pragma unroll
    for (int i = 0; i < 16; i++) {
        float4 v = kp[i];
        kkr[i*4] = v.x; kkr[i*4+1] = v.y; kkr[i*4+2] = v.z; kkr[i*4+3] = v.w;
    }

    double local = 0.0;
#pragma unroll
    for (int g = 0; g < G_; g++) {
        float d = 0.f;
#pragma unroll
        for (int e = 0; e < 64; e++) d += csS[g * 64 + e] * kkr[e];
        d *= 0.125f;
        g_scores[((size_t)(bh * G_ + g)) * S_ + s] = d;
        local += (double)d;
    }

    __shared__ double sh[128];
    sh[tid] = local;
    __syncthreads();
    for (int o = 64; o; o >>= 1) {
        if (tid < o) sh[tid] += sh[tid + o];
        __syncthreads();
    }
    if (tid == 0) g_partial[stile * G_ + bh] = sh[0];
}

__global__ __launch_bounds__(256) void mean_kernel()
{
    __shared__ double sh[256];
    int t = threadIdx.x;
    sh[t] = g_partial[t];
    __syncthreads();
    for (int o = 128; o; o >>= 1) {
        if (t < o) sh[t] += sh[t + o];
        __syncthreads();
    }
    if (t == 0) g_mean = (float)(sh[0] / (double)((size_t)NCHAIN * S_));
}

__global__ __launch_bounds__(256) void wexp_kernel()
{
    int i = blockIdx.x * 256 + threadIdx.x;
    g_wexp[i] = expf(g_scores[i] - g_mean);
}

// ---------------- chunk sums ----------------
__global__ __launch_bounds__(512) void chunk_sums_kernel()
{
    int bh = blockIdx.x, c = blockIdx.y;
    int tid = threadIdx.x;
    int g = tid >> 5, lane = tid & 31;

    __shared__ float kkS[CT * 64], vsS[CT * 64];
    ((float4*)kkS)[tid] = ((const float4*)(g_kk + ((size_t)bh * S_ + c * CT) * 64))[tid];
    ((float4*)vsS)[tid] = ((const float4*)(g_vs + ((size_t)bh * S_ + c * CT) * 64))[tid];

    int chain = bh * G_ + g;
    float wreg = g_wexp[(size_t)chain * S_ + c * CT + lane];
    __syncthreads();

    float nw = 0.f, ak0 = 0.f, ak1 = 0.f, av0 = 0.f, av1 = 0.f;
#pragma unroll
    for (int t = 0; t < CT; t++) {
        float w = __shfl_sync(0xffffffffu, wreg, t);
        nw += w;
        ak0 += w * kkS[t * 64 + lane];
        ak1 += w * kkS[t * 64 + lane + 32];
        av0 += w * vsS[t * 64 + lane];
        av1 += w * vsS[t * 64 + lane + 32];
    }
    float* op = g_chunk + ((size_t)chain * CH + c) * REC;
    op[1 + lane]  = ak0;
    op[33 + lane] = ak1;
    op[65 + lane] = av0;
    op[97 + lane] = av1;
    if (lane == 0) op[0] = nw;
}

__global__ __launch_bounds__(160) void chunk_prefix_kernel()
{
    int chain = blockIdx.x;
    int t = threadIdx.x;
    if (t >= 129) return;
    float run = 0.f;
    for (int c = 0; c < CH; c++) {
        size_t idx = ((size_t)chain * CH + c) * REC + t;
        float v = g_chunk[idx];
        g_chunk[idx] = run;
        run += v;
    }
}

// ---------------- attn_scan v3: 4 barriers, direct bf16 output -------------
// out(t) = sum_g c_g(t)*Sv0_g + sum_{tau<=t} (sum_g c_g(t)*w_g(tau)) * vs(tau)
__global__ __launch_bounds__(512) void attn_scan_kernel()
{
    int bh = blockIdx.x, c = blockIdx.y;
    int tid = threadIdx.x;
    int g = tid >> 5, lane = tid & 31;

    __shared__ float kkS[CT * 64], vsS[CT * 64], qsS[CT * 64];
    __shared__ float Sv0[G_][64];
    __shared__ float Lg[CT][17];
    __shared__ float Nn[CT][17];
    __shared__ float Cc[CT][17];
    __shared__ float Wsm[G_][CT + 1];
    __shared__ float Mm[CT][CT + 1];

    const float* kkBase = g_kk + ((size_t)bh * S_ + c * CT) * E_;
    const float* vsBase = g_vs + ((size_t)bh * S_ + c * CT) * E_;
    const float* qsBase = g_qs + ((size_t)bh * S_ + c * CT) * E_;
    ((float4*)kkS)[tid] = ((const float4*)kkBase)[tid];
    ((float4*)vsS)[tid] = ((const float4*)vsBase)[tid];
    ((float4*)qsS)[tid] = ((const float4*)qsBase)[tid];

    const float* pf = g_chunk + ((size_t)(bh * G_ + g) * CH + c) * REC;
    float nw  = pf[0];
    float skA = pf[1 + lane];
    float skB = pf[33 + lane];
    Sv0[g][lane]      = pf[65 + lane];
    Sv0[g][lane + 32] = pf[97 + lane];
    float wchunk = g_wexp[(size_t)(bh * G_ + g) * S_ + c * CT + lane];
    Wsm[g][lane] = wchunk;
    __syncthreads();

    // phase 1: per-warp Sk scan + logits (no block barriers)
#pragma unroll
    for (int t = 0; t < CT; t++) {
        float w = __shfl_sync(0xffffffffu, wchunk, t);
        nw  += w;
        skA += w * kkS[t * 64 + lane];
        skB += w * kkS[t * 64 + lane + 32];
        float d = qsS[t * 64 + lane] * skA + qsS[t * 64 + lane + 32] * skB;
#pragma unroll
        for (int o = 16; o; o >>= 1) d += __shfl_xor_sync(0xffffffffu, d, o);
        if (lane == 0) {
            float nwc = fmaxf(nw, 1e-8f);
            Lg[t][g] = d / nwc;
            Nn[t][g] = nwc;
        }
    }
    __syncthreads();

    // phase 2: softmax over g, one half-warp per step
    {
        int t2 = 2 * g + (lane >> 4);
        int gg = lane & 15;
        float x = Lg[t2][gg];
        float m = x;
#pragma unroll
        for (int o = 8; o; o >>= 1) m = fmaxf(m, __shfl_xor_sync(0xffffffffu, m, o));
        float e = expf(x - m);
        float ss = e;
#pragma unroll
        for (int o = 8; o; o >>= 1) ss += __shfl_xor_sync(0xffffffffu, ss, o);
        Cc[t2][gg] = (e / ss) / Nn[t2][gg];
    }
    __syncthreads();

    // phase 3a: M[t][tau] = sum_g Cc[t][g] * W[g][tau]
#pragma unroll
    for (int r = 0; r < 2; r++) {
        int idx = tid + r * 512;
        int t = idx >> 5, tau = idx & 31;
        float m = 0.f;
#pragma unroll
        for (int gg = 0; gg < G_; gg++) m += Cc[t][gg] * Wsm[gg][tau];
        Mm[t][tau] = m;
    }
    __syncthreads();

    // phase 3b: out[t][e] = sum_g Cc[t][g]*Sv0[g][e] + sum_{tau<=t} M[t][tau]*vs[tau][e]
    {
        int t  = tid >> 4;
        int eg = (tid & 15) * 4;
        float a0 = 0.f, a1 = 0.f, a2 = 0.f, a3 = 0.f;
#pragma unroll
        for (int gg = 0; gg < G_; gg++) {
            float cg = Cc[t][gg];
            float4 sv = *(const float4*)&Sv0[gg][eg];
            a0 += cg * sv.x; a1 += cg * sv.y; a2 += cg * sv.z; a3 += cg * sv.w;
        }
        for (int tau = 0; tau <= t; tau++) {
            float m = Mm[t][tau];
            float4 vv = *(const float4*)&vsS[tau * 64 + eg];
            a0 += m * vv.x; a1 += m * vv.y; a2 += m * vv.z; a3 += m * vv.w;
        }
        float h0,h1,h2,h3,l0,l1,l2,l3;
        split1(a0,h0,l0); split1(a1,h1,l1); split1(a2,h2,l2); split1(a3,h3,l3);
        int b = bh >> 3, h = bh & 7;
        size_t off = ((size_t)b * S_ + c * CT + t) * DM + h * 64 + eg;
        __nv_bfloat16* ahp = (__nv_bfloat16*)g_ah4;
        __nv_bfloat16* alp = (__nv_bfloat16*)g_al4;
        *(uint2*)(ahp + off) = make_uint2(pack2(h0,h1), pack2(h2,h3));
        *(uint2*)(alp + off) = make_uint2(pack2(l0,l1), pack2(l2,l3));
    }
}

// ---------------- launch ---------------------------------------------------
extern "C" void kernel_launch(void* const* d_in, const int* in_sizes, int n_in,
                              void* d_out, int out_size)
{
    const float* q   = (const float*)d_in[0];
    const float* k   = (const float*)d_in[1];
    const float* v   = (const float*)d_in[2];
    const float* ctx = (const float*)d_in[3];

    typedef __nv_bfloat16 bf;
    static float *p_qs = nullptr, *p_kk, *p_vs, *p_cs;
    static bf *qh,*ql,*kh,*kl,*vh,*vl,*ch,*cl;
    static bf *wqh,*wql,*wkh,*wkl,*wvh,*wvl,*woh,*wol,*wch,*wcl;
    static bf *ah,*al;
    if (!p_qs) {
        cudaGetSymbolAddress((void**)&p_qs,   g_qs);
        cudaGetSymbolAddress((void**)&p_kk,   g_kk);
        cudaGetSymbolAddress((void**)&p_vs,   g_vs);
        cudaGetSymbolAddress((void**)&p_cs,   g_cs);
        cudaGetSymbolAddress((void**)&qh, g_qh4);  cudaGetSymbolAddress((void**)&ql, g_ql4);
        cudaGetSymbolAddress((void**)&kh, g_kh4);  cudaGetSymbolAddress((void**)&kl, g_kl4);
        cudaGetSymbolAddress((void**)&vh, g_vh4);  cudaGetSymbolAddress((void**)&vl, g_vl4);
        cudaGetSymbolAddress((void**)&ch, g_ch4);  cudaGetSymbolAddress((void**)&cl, g_cl4);
        cudaGetSymbolAddress((void**)&wqh, g_wqh4); cudaGetSymbolAddress((void**)&wql, g_wql4);
        cudaGetSymbolAddress((void**)&wkh, g_wkh4); cudaGetSymbolAddress((void**)&wkl, g_wkl4);
        cudaGetSymbolAddress((void**)&wvh, g_wvh4); cudaGetSymbolAddress((void**)&wvl, g_wvl4);
        cudaGetSymbolAddress((void**)&woh, g_woh4); cudaGetSymbolAddress((void**)&wol, g_wol4);
        cudaGetSymbolAddress((void**)&wch, g_wch4); cudaGetSymbolAddress((void**)&wcl, g_wcl4);
        cudaGetSymbolAddress((void**)&ah, g_ah4);   cudaGetSymbolAddress((void**)&al, g_al4);
        cudaFuncSetAttribute(mma_gemm_multi, cudaFuncAttributeMaxDynamicSharedMemorySize, GSMEM_BYTES);
        cudaFuncSetAttribute(mma_gemm_one,   cudaFuncAttributeMaxDynamicSharedMemorySize, GSMEM_BYTES);
    }

    const unsigned N_BIG = (B_*S_*DM)/4;
    const unsigned N_CTX = (B_*G_*DM)/4;

    Conv4 c4;
    c4.seg[0] = { q,   qh, ql, N_BIG };
    c4.seg[1] = { k,   kh, kl, N_BIG };
    c4.seg[2] = { v,   vh, vl, N_BIG };
    c4.seg[3] = { ctx, ch, cl, N_CTX };
    unsigned total4 = 3 * N_BIG + N_CTX;
    convert_act<<<(total4 + 255) / 256, 256>>>(c4, total4);

    WT5 wt;
    wt.w[0] = (const float*)d_in[4]; wt.h[0] = wqh; wt.l[0] = wql;
    wt.w[1] = (const float*)d_in[5]; wt.h[1] = wkh; wt.l[1] = wkl;
    wt.w[2] = (const float*)d_in[6]; wt.h[2] = wvh; wt.l[2] = wvl;
    wt.w[3] = (const float*)d_in[7]; wt.h[3] = woh; wt.l[3] = wol;
    wt.w[4] = (const float*)d_in[8]; wt.h[4] = wch; wt.l[4] = wcl;
    convert_wT<<<dim3(16, 16, 5), 256>>>(wt);

    Gemm4 P;
    P.e[0] = { ch, cl, wch, wcl, p_cs, B_ * G_, G_, 1 };
    P.e[1] = { qh, ql, wqh, wql, p_qs, B_ * S_, S_, 1 };
    P.e[2] = { kh, kl, wkh, wkl, p_kk, B_ * S_, S_, 1 };
    P.e[3] = { vh, vl, wvh, wvl, p_vs, B_ * S_, S_, 1 };
    mma_gemm_multi<<<dim3(193, 4), 256, GSMEM_BYTES>>>(P);

    scores_kernel<<<dim3(G_, 16), 128>>>();
    mean_kernel<<<1, 256>>>();
    wexp_kernel<<<(NCHAIN * S_) / 256, 256>>>();
    chunk_sums_kernel<<<dim3(G_, CH), 512>>>();
    chunk_prefix_kernel<<<NCHAIN, 160>>>();
    attn_scan_kernel<<<dim3(B_ * H_, CH), 512>>>();

    GemmEnt Qo = { ah, al, woh, wol, (float*)d_out, B_ * S_, S_, 0 };
    mma_gemm_one<<<dim3(64, 4), 256, GSMEM_BYTES>>>(Qo);
}